// round 4
// baseline (speedup 1.0000x reference)
#include <cuda_runtime.h>
#include <math.h>

// ---------------- problem constants ----------------
#define BI    4
#define NN    1024
#define DIN   2048
#define SD    512
#define NH    8
#define NF    8
#define NC    20
#define NODES (BI*NN)            // 4096
#define WALLN 876                // 512 sim | 64 gat1 | 60 ref | 240 bbox
#define WALLP 896                // padded to 14*64
#define COL_H1   512
#define COL_REF  576
#define COL_BBOX 636

// output layout (flattened tuple, f32)
#define OUT_NODE  80
#define OUT_REF   82000
#define OUT_BBOX  327760

// smem staging strides (floats). 36 = 9x16B: each quad-phase of a warp hits
// 8 distinct bank-groups for 16B cp.async stores, and (4m+k)&31 == lane for
// the 4B fragment gathers -> conflict-free both ways.
#define TSTR 36
#define A_TILE (128*TSTR)
#define B_TILE (64*TSTR)
#define SMEM_BYTES ((2*A_TILE + 2*B_TILE)*4)   // 55296

// ---------------- scratch (static device memory; no allocs) ----------------
__device__ float g_Wt[(size_t)WALLP*DIN];        // transposed packed weights [896][2048]
__device__ float g_Call[(size_t)NODES*WALLP];    // packed GEMM out [4096][896]
__device__ float g_SF[NODES*SD];         // normalized sim features
__device__ float g_ES1[NODES*NH];
__device__ float g_ED1[NODES*NH];
__device__ unsigned g_M1[BI*NH];         // encoded per-(img,head) max of es1
__device__ float g_N1[NODES*64];         // elu(gat1 out)
__device__ float g_H2[NODES*NC];
__device__ float g_ES2[NODES];
__device__ float g_ED2[NODES];
__device__ unsigned g_M2[BI];
__device__ float g_N2[NODES*NC];
__device__ unsigned char g_iouM[(size_t)BI*NN*NN];
__device__ unsigned char g_simM[(size_t)BI*NN*NN];

// monotonic float<->uint encoding for atomicMax
__device__ __forceinline__ unsigned fenc(float f) {
    unsigned u = __float_as_uint(f);
    return (u & 0x80000000u) ? ~u : (u | 0x80000000u);
}
__device__ __forceinline__ float fdec(unsigned u) {
    u = (u & 0x80000000u) ? (u & 0x7fffffffu) : ~u;
    return __uint_as_float(u);
}
__device__ __forceinline__ float lrelu(float x) { return x > 0.f ? x : 0.2f * x; }

__device__ __forceinline__ unsigned to_tf32(float f) {
    unsigned h; asm("cvt.rna.tf32.f32 %0, %1;" : "=r"(h) : "f"(f));
    return h;
}

#define MMA_TF32(c, a, b)                                                   \
    asm("mma.sync.aligned.m16n8k8.row.col.f32.tf32.tf32.f32 "               \
        "{%0,%1,%2,%3}, {%4,%5,%6,%7}, {%8,%9}, {%0,%1,%2,%3};"             \
        : "+f"((c)[0]), "+f"((c)[1]), "+f"((c)[2]), "+f"((c)[3])            \
        : "r"((a)[0]), "r"((a)[1]), "r"((a)[2]), "r"((a)[3]),               \
          "r"((b)[0]), "r"((b)[1]))

#define CP16(dst, src)                                                      \
    asm volatile("cp.async.cg.shared.global [%0], [%1], 16;"                \
                 :: "r"(dst), "l"(src))
#define CP_COMMIT() asm volatile("cp.async.commit_group;")
#define CP_WAIT1()  asm volatile("cp.async.wait_group 1;")
#define CP_WAIT0()  asm volatile("cp.async.wait_group 0;")

// ---------------- kernels ----------------
__global__ void init_kernel() {
    int t = threadIdx.x;
    if (t < BI*NH) g_M1[t] = 0u;
    if (t < BI)    g_M2[t] = 0u;
}

// pack weights transposed: g_Wt[n][k], n in [0,896). Tiled transpose, coalesced
// both sides (sources are all k-major with contiguous column index).
__global__ void pack_kernel(const float* __restrict__ simW, const float* __restrict__ gat1W,
                            const float* __restrict__ refW, const float* __restrict__ bboxW) {
    __shared__ float tile[32][33];
    int nt = blockIdx.x * 32, kt = blockIdx.y * 32;
    int tx = threadIdx.x, ty = threadIdx.y;   // 32x8
#pragma unroll
    for (int r = 0; r < 4; r++) {
        int k = kt + ty + r * 8;
        int n = nt + tx;
        float v = 0.f;
        if (n < COL_H1)        v = simW[(size_t)k*SD + n];
        else if (n < COL_REF)  v = gat1W[(size_t)k*64 + (n - COL_H1)];
        else if (n < COL_BBOX) { int jj = n - COL_REF;  int t3 = jj/NC; int c = jj%NC;
                                 v = refW[(size_t)t3*DIN*NC + (size_t)k*NC + c]; }
        else if (n < WALLN)    { int jj = n - COL_BBOX; int t3 = jj/80; int c = jj%80;
                                 v = bboxW[(size_t)t3*DIN*80 + (size_t)k*80 + c]; }
        tile[ty + r * 8][tx] = v;
    }
    __syncthreads();
#pragma unroll
    for (int r = 0; r < 4; r++) {
        int n = nt + ty + r * 8;
        int k = kt + tx;
        g_Wt[(size_t)n*DIN + k] = tile[tx][ty + r * 8];
    }
}

// Merged GEMM: g_Call[4096,896] = A[4096,2048] @ g_Wt^T. tf32 mma.sync,
// BM=128 BN=64 BK=32, cp.async double-buffered. Blocks with n0>=512 do the
// 3x-tf32 split (output-critical columns); n0<512 single-pass (mask-only).
__global__ __launch_bounds__(256, 2) void sgemm_tc_pipe(const float* __restrict__ A) {
    extern __shared__ float sm[];
    float* AsB = sm;                  // [2][128*36]
    float* BsB = sm + 2 * A_TILE;     // [2][64*36]
    const int t = threadIdx.x;
    const int lane = t & 31, w = t >> 5;
    const int wm = w >> 1, wn = w & 1;
    const int m0 = blockIdx.y * 128;
    const int n0 = blockIdx.x * 64;
    const bool three = (n0 >= COL_H1);

    const float* Abase = A + (size_t)m0 * DIN;
    const float* Bbase = g_Wt + (size_t)n0 * DIN;

    float acc[2][4][4];
#pragma unroll
    for (int mt = 0; mt < 2; mt++)
#pragma unroll
        for (int nt = 0; nt < 4; nt++)
#pragma unroll
            for (int i = 0; i < 4; i++) acc[mt][nt][i] = 0.f;

    auto stage = [&](int kt, int buf) {
        float* ad = AsB + buf * A_TILE;
        float* bd = BsB + buf * B_TILE;
        int kk = kt * 32;
#pragma unroll
        for (int j = 0; j < 4; j++) {
            int idx = t + j * 256;
            int m = idx >> 3, ch = (idx & 7) << 2;
            unsigned d = (unsigned)__cvta_generic_to_shared(ad + m * TSTR + ch);
            CP16(d, Abase + (size_t)m * DIN + kk + ch);
        }
#pragma unroll
        for (int j = 0; j < 2; j++) {
            int idx = t + j * 256;
            int n = idx >> 3, ch = (idx & 7) << 2;
            unsigned d = (unsigned)__cvta_generic_to_shared(bd + n * TSTR + ch);
            CP16(d, Bbase + (size_t)n * DIN + kk + ch);
        }
    };

    stage(0, 0);
    CP_COMMIT();
    const int T = DIN / 32;
    for (int kt = 0; kt < T; kt++) {
        int cur = kt & 1;
        if (kt + 1 < T) {
            stage(kt + 1, cur ^ 1);
            CP_COMMIT();
            CP_WAIT1();
        } else {
            CP_WAIT0();
        }
        __syncthreads();
        const float* a_s = AsB + cur * A_TILE;
        const float* b_s = BsB + cur * B_TILE;
#pragma unroll
        for (int ks = 0; ks < 4; ks++) {
            unsigned ah[2][4], al[2][4], bh[4][2], bl[4][2];
#pragma unroll
            for (int mt = 0; mt < 2; mt++)
#pragma unroll
                for (int i = 0; i < 4; i++) {
                    int m = wm*32 + mt*16 + (lane >> 2) + ((i & 1) << 3);
                    int k = ks*8 + (lane & 3) + ((i >> 1) << 2);
                    float f = a_s[m * TSTR + k];
                    ah[mt][i] = to_tf32(f);
                    if (three) al[mt][i] = to_tf32(f - __uint_as_float(ah[mt][i]));
                }
#pragma unroll
            for (int nt = 0; nt < 4; nt++)
#pragma unroll
                for (int i = 0; i < 2; i++) {
                    int n = wn*32 + nt*8 + (lane >> 2);
                    int k = ks*8 + (lane & 3) + (i << 2);
                    float f = b_s[n * TSTR + k];
                    bh[nt][i] = to_tf32(f);
                    if (three) bl[nt][i] = to_tf32(f - __uint_as_float(bh[nt][i]));
                }
#pragma unroll
            for (int mt = 0; mt < 2; mt++)
#pragma unroll
                for (int nt = 0; nt < 4; nt++) {
                    MMA_TF32(acc[mt][nt], ah[mt], bh[nt]);
                    if (three) {
                        MMA_TF32(acc[mt][nt], al[mt], bh[nt]);
                        MMA_TF32(acc[mt][nt], ah[mt], bl[nt]);
                    }
                }
        }
        __syncthreads();
    }
#pragma unroll
    for (int mt = 0; mt < 2; mt++)
#pragma unroll
        for (int nt = 0; nt < 4; nt++) {
            int row = m0 + wm*32 + mt*16 + (lane >> 2);
            int col = n0 + wn*32 + nt*8 + ((lane & 3) << 1);
            *(float2*)&g_Call[(size_t)row * WALLP + col] =
                make_float2(acc[mt][nt][0], acc[mt][nt][1]);
            *(float2*)&g_Call[(size_t)(row + 8) * WALLP + col] =
                make_float2(acc[mt][nt][2], acc[mt][nt][3]);
        }
}

// per-row L2 normalize of sim features (adds sim_b)
__global__ void normalize_kernel(const float* __restrict__ simb) {
    int r = blockIdx.x, tid = threadIdx.x;  // 128 threads
    const float* row = g_Call + (size_t)r * WALLP;
    float ss = 0.f;
    for (int c = tid; c < SD; c += 128) { float v = row[c] + simb[c]; ss += v * v; }
#pragma unroll
    for (int off = 16; off > 0; off >>= 1) ss += __shfl_xor_sync(0xffffffffu, ss, off);
    __shared__ float red[4];
    if ((tid & 31) == 0) red[tid >> 5] = ss;
    __syncthreads();
    float tot = red[0] + red[1] + red[2] + red[3];
    float inv = 1.f / (sqrtf(tot) + 1e-9f);
    for (int c = tid; c < SD; c += 128) {
        float v = row[c] + simb[c];
        g_SF[(size_t)r * SD + c] = v * inv;
    }
}

__global__ void edge1_kernel(const float* __restrict__ asrc, const float* __restrict__ adst) {
    int n = blockIdx.x * blockDim.x + threadIdx.x;
    if (n >= NODES) return;
    const float* h = g_Call + (size_t)n * WALLP + COL_H1;
    int img = n >> 10;
#pragma unroll
    for (int hh = 0; hh < NH; hh++) {
        float es = 0.f, ed = 0.f;
#pragma unroll
        for (int f = 0; f < NF; f++) {
            float v = h[hh * NF + f];
            es = fmaf(v, asrc[hh * NF + f], es);
            ed = fmaf(v, adst[hh * NF + f], ed);
        }
        g_ES1[n * NH + hh] = es;
        g_ED1[n * NH + hh] = ed;
        atomicMax(&g_M1[img * NH + hh], fenc(es));
    }
}

// IoU edge mask (byte per pair), 16 dsts per block
__global__ void iou_kernel(const float* __restrict__ boxes) {
    __shared__ float4 bx[NN];
    int img = blockIdx.y, tid = threadIdx.x;
    const float4* bsrc = (const float4*)(boxes + (size_t)img * NN * 4);
    for (int i = tid; i < NN; i += 256) bx[i] = bsrc[i];
    __syncthreads();
    unsigned char* M = g_iouM + (size_t)img * NN * NN;
    for (int idx = tid; idx < 16 * NN; idx += 256) {
        int dl = idx >> 10, s = idx & 1023;
        int d = blockIdx.x * 16 + dl;
        float4 A = bx[d], Bb = bx[s];
        float areaA = (A.z - A.x) * (A.w - A.y);
        float areaB = (Bb.z - Bb.x) * (Bb.w - Bb.y);
        float lx = fmaxf(A.x, Bb.x), ly = fmaxf(A.y, Bb.y);
        float rx = fminf(A.z, Bb.z), ry = fminf(A.w, Bb.w);
        float w = fmaxf(rx - lx, 0.f), hh = fmaxf(ry - ly, 0.f);
        float inter = w * hh;
        float iou = inter / (areaA + areaB - inter + 1e-9f);
        M[(size_t)d * NN + s] = (unsigned char)((iou >= 0.4f) || (s == d));
    }
}

// GAT1 aggregation: warp per dst, 8 dsts per block, smem-staged src chunks
__global__ __launch_bounds__(256) void gat1_agg_kernel(const float* __restrict__ b1) {
    int img = blockIdx.y;
    int warp = threadIdx.x >> 5, lane = threadIdx.x & 31;
    int d = blockIdx.x * 8 + warp;
    int gd = img * NN + d;
    __shared__ float sh_h1[128][65];
    __shared__ float sh_es[128][9];
    __shared__ unsigned char sh_m[8][128];
    float acc[64], den[NH], ed[NH], shift[NH];
#pragma unroll
    for (int i = 0; i < 64; i++) acc[i] = 0.f;
#pragma unroll
    for (int h = 0; h < NH; h++) {
        den[h] = 0.f;
        ed[h] = g_ED1[gd * NH + h];
        shift[h] = lrelu(fdec(g_M1[img * NH + h]) + ed[h]);
    }
    for (int c0 = 0; c0 < NN; c0 += 128) {
        __syncthreads();
        for (int i = threadIdx.x; i < 128 * 64; i += 256) {
            int r = i >> 6, c = i & 63;
            sh_h1[r][c] = g_Call[(size_t)(img * NN + c0 + r) * WALLP + COL_H1 + c];
        }
        for (int i = threadIdx.x; i < 128 * 8; i += 256) {
            int r = i >> 3, c = i & 7;
            sh_es[r][c] = g_ES1[(img * NN + c0 + r) * NH + c];
        }
        {
            const unsigned* mrow = (const unsigned*)(g_iouM + (size_t)img * NN * NN + (size_t)d * NN + c0);
            ((unsigned*)sh_m[warp])[lane] = mrow[lane];
        }
        __syncthreads();
        for (int p = 0; p < 4; p++) {
            int sl = p * 32 + lane;
            bool mb = sh_m[warp][sl] != 0;
            if (!__any_sync(0xffffffffu, mb)) continue;
            if (mb) {
#pragma unroll
                for (int h = 0; h < NH; h++) {
                    float w = __expf(lrelu(sh_es[sl][h] + ed[h]) - shift[h]);
                    den[h] += w;
#pragma unroll
                    for (int f = 0; f < NF; f++)
                        acc[h * 8 + f] = fmaf(w, sh_h1[sl][h * 8 + f], acc[h * 8 + f]);
                }
            }
        }
    }
#pragma unroll
    for (int off = 16; off > 0; off >>= 1) {
#pragma unroll
        for (int i = 0; i < 64; i++) acc[i] += __shfl_xor_sync(0xffffffffu, acc[i], off);
#pragma unroll
        for (int h = 0; h < NH; h++) den[h] += __shfl_xor_sync(0xffffffffu, den[h], off);
    }
    if (lane == 0) {
#pragma unroll
        for (int i = 0; i < 64; i++) {
            float v = acc[i] / den[i >> 3] + b1[i];
            g_N1[(size_t)gd * 64 + i] = v > 0.f ? v : expm1f(v);
        }
    }
}

__global__ void gat2_prep_kernel(const float* __restrict__ W2,
                                 const float* __restrict__ asrc2,
                                 const float* __restrict__ adst2) {
    int n = blockIdx.x * blockDim.x + threadIdx.x;
    if (n >= NODES) return;
    int img = n >> 10;
    float x[64];
#pragma unroll
    for (int k = 0; k < 64; k++) x[k] = g_N1[(size_t)n * 64 + k];
    float es = 0.f, ed = 0.f;
    for (int c = 0; c < NC; c++) {
        float a = 0.f;
#pragma unroll
        for (int k = 0; k < 64; k++) a = fmaf(x[k], W2[k * NC + c], a);
        g_H2[n * NC + c] = a;
        es = fmaf(a, asrc2[c], es);
        ed = fmaf(a, adst2[c], ed);
    }
    g_ES2[n] = es;
    g_ED2[n] = ed;
    atomicMax(&g_M2[img], fenc(es));
}

// per-image gram of normalized sim features -> byte mask, tf32 tensor cores,
// cp.async double-buffered. BM=128(s) BN=64(d) BK=32, single pass.
__global__ __launch_bounds__(256, 2) void gram_tc_pipe() {
    extern __shared__ float sm[];
    float* AsB = sm;
    float* BsB = sm + 2 * A_TILE;
    const int img = blockIdx.z;
    const float* SF = g_SF + (size_t)img * NN * SD;
    const int t = threadIdx.x;
    const int lane = t & 31, w = t >> 5;
    const int wm = w >> 1, wn = w & 1;
    const int m0 = blockIdx.y * 128;   // source rows
    const int n0 = blockIdx.x * 64;    // destination rows

    const float* Abase = SF + (size_t)m0 * SD;
    const float* Bbase = SF + (size_t)n0 * SD;

    float acc[2][4][4];
#pragma unroll
    for (int mt = 0; mt < 2; mt++)
#pragma unroll
        for (int nt = 0; nt < 4; nt++)
#pragma unroll
            for (int i = 0; i < 4; i++) acc[mt][nt][i] = 0.f;

    auto stage = [&](int kt, int buf) {
        float* ad = AsB + buf * A_TILE;
        float* bd = BsB + buf * B_TILE;
        int kk = kt * 32;
#pragma unroll
        for (int j = 0; j < 4; j++) {
            int idx = t + j * 256;
            int m = idx >> 3, ch = (idx & 7) << 2;
            unsigned d = (unsigned)__cvta_generic_to_shared(ad + m * TSTR + ch);
            CP16(d, Abase + (size_t)m * SD + kk + ch);
        }
#pragma unroll
        for (int j = 0; j < 2; j++) {
            int idx = t + j * 256;
            int n = idx >> 3, ch = (idx & 7) << 2;
            unsigned d = (unsigned)__cvta_generic_to_shared(bd + n * TSTR + ch);
            CP16(d, Bbase + (size_t)n * SD + kk + ch);
        }
    };

    stage(0, 0);
    CP_COMMIT();
    const int T = SD / 32;
    for (int kt = 0; kt < T; kt++) {
        int cur = kt & 1;
        if (kt + 1 < T) {
            stage(kt + 1, cur ^ 1);
            CP_COMMIT();
            CP_WAIT1();
        } else {
            CP_WAIT0();
        }
        __syncthreads();
        const float* a_s = AsB + cur * A_TILE;
        const float* b_s = BsB + cur * B_TILE;
#pragma unroll
        for (int ks = 0; ks < 4; ks++) {
            unsigned ah[2][4], bh[4][2];
#pragma unroll
            for (int mt = 0; mt < 2; mt++)
#pragma unroll
                for (int i = 0; i < 4; i++) {
                    int m = wm*32 + mt*16 + (lane >> 2) + ((i & 1) << 3);
                    int k = ks*8 + (lane & 3) + ((i >> 1) << 2);
                    ah[mt][i] = to_tf32(a_s[m * TSTR + k]);
                }
#pragma unroll
            for (int nt = 0; nt < 4; nt++)
#pragma unroll
                for (int i = 0; i < 2; i++) {
                    int n = wn*32 + nt*8 + (lane >> 2);
                    int k = ks*8 + (lane & 3) + (i << 2);
                    bh[nt][i] = to_tf32(b_s[n * TSTR + k]);
                }
#pragma unroll
            for (int mt = 0; mt < 2; mt++)
#pragma unroll
                for (int nt = 0; nt < 4; nt++)
                    MMA_TF32(acc[mt][nt], ah[mt], bh[nt]);
        }
        __syncthreads();
    }
    unsigned char* M = g_simM + (size_t)img * NN * NN;
#pragma unroll
    for (int mt = 0; mt < 2; mt++)
#pragma unroll
        for (int nt = 0; nt < 4; nt++) {
            int s0 = m0 + wm*32 + mt*16 + (lane >> 2);
            int d0 = n0 + wn*32 + nt*8 + ((lane & 3) << 1);
            M[(size_t)d0 * NN + s0]       = (unsigned char)((acc[mt][nt][0] >= 0.4f) || (s0 == d0));
            M[(size_t)(d0+1) * NN + s0]   = (unsigned char)((acc[mt][nt][1] >= 0.4f) || (s0 == d0+1));
            M[(size_t)d0 * NN + s0+8]     = (unsigned char)((acc[mt][nt][2] >= 0.4f) || (s0+8 == d0));
            M[(size_t)(d0+1) * NN + s0+8] = (unsigned char)((acc[mt][nt][3] >= 0.4f) || (s0+8 == d0+1));
        }
}

__global__ __launch_bounds__(256) void gat2_agg_kernel(const float* __restrict__ b2) {
    int img = blockIdx.y;
    int warp = threadIdx.x >> 5, lane = threadIdx.x & 31;
    int d = blockIdx.x * 8 + warp;
    int gd = img * NN + d;
    __shared__ float sh_h2[128][21];
    __shared__ float sh_es[128];
    __shared__ unsigned char sh_m[8][128];
    float acc[NC], den = 0.f;
#pragma unroll
    for (int c = 0; c < NC; c++) acc[c] = 0.f;
    float ed = g_ED2[gd];
    float shift = lrelu(fdec(g_M2[img]) + ed);
    for (int c0 = 0; c0 < NN; c0 += 128) {
        __syncthreads();
        for (int i = threadIdx.x; i < 128 * NC; i += 256) {
            int r = i / NC, c = i % NC;
            sh_h2[r][c] = g_H2[(img * NN + c0 + r) * NC + c];
        }
        if (threadIdx.x < 128) sh_es[threadIdx.x] = g_ES2[img * NN + c0 + threadIdx.x];
        {
            const unsigned* mrow = (const unsigned*)(g_simM + (size_t)img * NN * NN + (size_t)d * NN + c0);
            ((unsigned*)sh_m[warp])[lane] = mrow[lane];
        }
        __syncthreads();
        for (int p = 0; p < 4; p++) {
            int sl = p * 32 + lane;
            bool mb = sh_m[warp][sl] != 0;
            if (!__any_sync(0xffffffffu, mb)) continue;
            if (mb) {
                float w = __expf(lrelu(sh_es[sl] + ed) - shift);
                den += w;
#pragma unroll
                for (int c = 0; c < NC; c++) acc[c] = fmaf(w, sh_h2[sl][c], acc[c]);
            }
        }
    }
#pragma unroll
    for (int off = 16; off > 0; off >>= 1) {
#pragma unroll
        for (int c = 0; c < NC; c++) acc[c] += __shfl_xor_sync(0xffffffffu, acc[c], off);
        den += __shfl_xor_sync(0xffffffffu, den, off);
    }
    if (lane == 0) {
#pragma unroll
        for (int c = 0; c < NC; c++) g_N2[(size_t)gd * NC + c] = acc[c] / den + b2[c];
    }
}

__global__ void node_kernel(const float* __restrict__ nW, const float* __restrict__ nb,
                            float* __restrict__ out) {
    int n = blockIdx.x * blockDim.x + threadIdx.x;
    if (n >= NODES) return;
    float x[NC], v[NC];
#pragma unroll
    for (int c = 0; c < NC; c++) x[c] = g_N2[(size_t)n * NC + c];
#pragma unroll
    for (int c = 0; c < NC; c++) {
        float a = nb[c];
#pragma unroll
        for (int cc = 0; cc < NC; cc++) a = fmaf(x[cc], nW[cc * NC + c], a);
        v[c] = a;
    }
    float m = v[0];
#pragma unroll
    for (int c = 1; c < NC; c++) m = fmaxf(m, v[c]);
    float s = 0.f;
#pragma unroll
    for (int c = 0; c < NC; c++) { v[c] = __expf(v[c] - m); s += v[c]; }
    float inv = 1.f / s;
#pragma unroll
    for (int c = 0; c < NC; c++) out[OUT_NODE + (size_t)n * NC + c] = v[c] * inv;
}

__global__ void graph_kernel(float* __restrict__ out) {
    int img = blockIdx.x, c = blockIdx.y, tid = threadIdx.x;  // 256 threads
    float s = 0.f;
    for (int node = tid; node < NN; node += 256)
        s += out[OUT_NODE + (size_t)(img * NN + node) * NC + c];
#pragma unroll
    for (int off = 16; off > 0; off >>= 1) s += __shfl_xor_sync(0xffffffffu, s, off);
    __shared__ float red[8];
    if ((tid & 31) == 0) red[tid >> 5] = s;
    __syncthreads();
    if (tid == 0) {
        float tot = 0.f;
#pragma unroll
        for (int i = 0; i < 8; i++) tot += red[i];
        out[img * NC + c] = tot * (1.f / (float)NN);
    }
}

__global__ void scatter_kernel(const float* __restrict__ refb, const float* __restrict__ bboxb,
                               float* __restrict__ out) {
    int idx = blockIdx.x * blockDim.x + threadIdx.x;
    const int REF_TOT = 3 * NODES * NC;       // 245760
    const int BBOX_TOT = 3 * NODES * 80;      // 983040
    if (idx < REF_TOT) {
        int k = idx / (NODES * NC), r = idx % (NODES * NC);
        int n = r / NC, c = r % NC;
        out[OUT_REF + idx] = g_Call[(size_t)n * WALLP + COL_REF + k * NC + c] + refb[k * NC + c];
    } else {
        int j = idx - REF_TOT;
        if (j >= BBOX_TOT) return;
        int k = j / (NODES * 80), r = j % (NODES * 80);
        int n = r / 80, c = r % 80;
        out[OUT_BBOX + j] = g_Call[(size_t)n * WALLP + COL_BBOX + k * 80 + c] + bboxb[k * 80 + c];
    }
}

// ---------------- launch ----------------
extern "C" void kernel_launch(void* const* d_in, const int* in_sizes, int n_in,
                              void* d_out, int out_size) {
    const float* x1     = (const float*)d_in[0];
    const float* boxes  = (const float*)d_in[1];
    const float* simW   = (const float*)d_in[2];
    const float* simb   = (const float*)d_in[3];
    const float* gat1W  = (const float*)d_in[4];
    const float* asrc1  = (const float*)d_in[5];
    const float* adst1  = (const float*)d_in[6];
    const float* b1     = (const float*)d_in[7];
    const float* gat2W  = (const float*)d_in[8];
    const float* asrc2  = (const float*)d_in[9];
    const float* adst2  = (const float*)d_in[10];
    const float* b2     = (const float*)d_in[11];
    const float* nodeW  = (const float*)d_in[12];
    const float* nodeb  = (const float*)d_in[13];
    const float* refW   = (const float*)d_in[14];
    const float* refb   = (const float*)d_in[15];
    const float* bboxW  = (const float*)d_in[16];
    const float* bboxb  = (const float*)d_in[17];
    float* out = (float*)d_out;

    cudaFuncSetAttribute(sgemm_tc_pipe, cudaFuncAttributeMaxDynamicSharedMemorySize, SMEM_BYTES);
    cudaFuncSetAttribute(gram_tc_pipe,  cudaFuncAttributeMaxDynamicSharedMemorySize, SMEM_BYTES);

    init_kernel<<<1, 64>>>();
    pack_kernel<<<dim3(WALLP / 32, DIN / 32), dim3(32, 8)>>>(simW, gat1W, refW, bboxW);
    iou_kernel<<<dim3(NN / 16, BI), 256>>>(boxes);
    sgemm_tc_pipe<<<dim3(WALLP / 64, NODES / 128), 256, SMEM_BYTES>>>(x1);
    normalize_kernel<<<NODES, 128>>>(simb);
    edge1_kernel<<<NODES / 256, 256>>>(asrc1, adst1);
    gat1_agg_kernel<<<dim3(NN / 8, BI), 256>>>(b1);
    gat2_prep_kernel<<<NODES / 256, 256>>>(gat2W, asrc2, adst2);
    gram_tc_pipe<<<dim3(NN / 64, NN / 128, BI), 256, SMEM_BYTES>>>();
    gat2_agg_kernel<<<dim3(NN / 8, BI), 256>>>(b2);
    node_kernel<<<NODES / 256, 256>>>(nodeW, nodeb, out);
    graph_kernel<<<dim3(BI, NC), 256>>>(out);
    scatter_kernel<<<(3 * NODES * NC + 3 * NODES * 80 + 255) / 256, 256>>>(refb, bboxb, out);
}

// round 5
// speedup vs baseline: 1.0544x; 1.0544x over previous
#include <cuda_runtime.h>
#include <math.h>

// ---------------- problem constants ----------------
#define BI    4
#define NN    1024
#define DIN   2048
#define SD    512
#define NH    8
#define NF    8
#define NC    20
#define NODES (BI*NN)            // 4096
#define WALLN 876                // 512 sim | 64 gat1 | 60 ref | 240 bbox
#define WALLP 896                // padded to 14*64
#define COL_H1   512
#define COL_REF  576
#define COL_BBOX 636

// output layout (flattened tuple, f32)
#define OUT_NODE  80
#define OUT_REF   82000
#define OUT_BBOX  327760

// smem staging stride (floats). 36 = 9x16B: conflict-free for 16B cp.async
// stores and for the 4B fragment gathers ((4m+k)&31 covers all banks).
#define TSTR 36
#define A_TILE (128*TSTR)
#define B_TILE (64*TSTR)
#define BUF    (2*A_TILE + 2*B_TILE)          // hi+lo for A and B (floats)
#define SMEM_BYTES (2*BUF*4)                  // 110592 B, double buffered

// ---------------- scratch (static device memory; no allocs) ----------------
__device__ float g_Ah[(size_t)NODES*DIN];        // tf32-rounded x1
__device__ float g_Al[(size_t)NODES*DIN];        // tf32 residual of x1
__device__ float g_Wth[(size_t)WALLP*DIN];       // transposed packed weights, hi
__device__ float g_Wtl[(size_t)WALLP*DIN];       // transposed packed weights, lo
__device__ float g_Call[(size_t)NODES*WALLP];    // packed GEMM out [4096][896]
__device__ float g_SF[NODES*SD];         // normalized sim features (tf32-rounded)
__device__ float g_ES1[NODES*NH];
__device__ float g_ED1[NODES*NH];
__device__ unsigned g_M1[BI*NH];         // encoded per-(img,head) max of es1
__device__ float g_N1[NODES*64];         // elu(gat1 out)
__device__ float g_H2[NODES*NC];
__device__ float g_ES2[NODES];
__device__ float g_ED2[NODES];
__device__ unsigned g_M2[BI];
__device__ float g_N2[NODES*NC];
__device__ unsigned char g_iouM[(size_t)BI*NN*NN];
__device__ unsigned char g_simM[(size_t)BI*NN*NN];

// monotonic float<->uint encoding for atomicMax
__device__ __forceinline__ unsigned fenc(float f) {
    unsigned u = __float_as_uint(f);
    return (u & 0x80000000u) ? ~u : (u | 0x80000000u);
}
__device__ __forceinline__ float fdec(unsigned u) {
    u = (u & 0x80000000u) ? (u & 0x7fffffffu) : ~u;
    return __uint_as_float(u);
}
__device__ __forceinline__ float lrelu(float x) { return x > 0.f ? x : 0.2f * x; }

__device__ __forceinline__ unsigned to_tf32(float f) {
    unsigned h; asm("cvt.rna.tf32.f32 %0, %1;" : "=r"(h) : "f"(f));
    return h;
}
__device__ __forceinline__ float tf32_hi(float f) { return __uint_as_float(to_tf32(f)); }

#define MMA_TF32(c, a, b)                                                   \
    asm("mma.sync.aligned.m16n8k8.row.col.f32.tf32.tf32.f32 "               \
        "{%0,%1,%2,%3}, {%4,%5,%6,%7}, {%8,%9}, {%0,%1,%2,%3};"             \
        : "+f"((c)[0]), "+f"((c)[1]), "+f"((c)[2]), "+f"((c)[3])            \
        : "r"((a)[0]), "r"((a)[1]), "r"((a)[2]), "r"((a)[3]),               \
          "r"((b)[0]), "r"((b)[1]))

#define CP16(dst, src)                                                      \
    asm volatile("cp.async.cg.shared.global [%0], [%1], 16;"                \
                 :: "r"(dst), "l"(src))
#define CP_COMMIT() asm volatile("cp.async.commit_group;")
#define CP_WAIT1()  asm volatile("cp.async.wait_group 1;")
#define CP_WAIT0()  asm volatile("cp.async.wait_group 0;")

// ---------------- kernels ----------------
__global__ void init_kernel() {
    int t = threadIdx.x;
    if (t < BI*NH) g_M1[t] = 0u;
    if (t < BI)    g_M2[t] = 0u;
}

// split x1 into tf32 hi/lo (f32 bit patterns already valid tf32 operands)
__global__ void splitA_kernel(const float* __restrict__ A) {
    int i = blockIdx.x * blockDim.x + threadIdx.x;   // float4 index
    float4 v = ((const float4*)A)[i];
    float4 h, l;
    h.x = tf32_hi(v.x); l.x = tf32_hi(v.x - h.x);
    h.y = tf32_hi(v.y); l.y = tf32_hi(v.y - h.y);
    h.z = tf32_hi(v.z); l.z = tf32_hi(v.z - h.z);
    h.w = tf32_hi(v.w); l.w = tf32_hi(v.w - h.w);
    ((float4*)g_Ah)[i] = h;
    ((float4*)g_Al)[i] = l;
}

// pack weights transposed + tf32-split: g_Wth/g_Wtl[n][k], n in [0,896).
__global__ void pack_kernel(const float* __restrict__ simW, const float* __restrict__ gat1W,
                            const float* __restrict__ refW, const float* __restrict__ bboxW) {
    __shared__ float tile[32][33];
    int nt = blockIdx.x * 32, kt = blockIdx.y * 32;
    int tx = threadIdx.x, ty = threadIdx.y;   // 32x8
#pragma unroll
    for (int r = 0; r < 4; r++) {
        int k = kt + ty + r * 8;
        int n = nt + tx;
        float v = 0.f;
        if (n < COL_H1)        v = simW[(size_t)k*SD + n];
        else if (n < COL_REF)  v = gat1W[(size_t)k*64 + (n - COL_H1)];
        else if (n < COL_BBOX) { int jj = n - COL_REF;  int t3 = jj/NC; int c = jj%NC;
                                 v = refW[(size_t)t3*DIN*NC + (size_t)k*NC + c]; }
        else if (n < WALLN)    { int jj = n - COL_BBOX; int t3 = jj/80; int c = jj%80;
                                 v = bboxW[(size_t)t3*DIN*80 + (size_t)k*80 + c]; }
        tile[ty + r * 8][tx] = v;
    }
    __syncthreads();
#pragma unroll
    for (int r = 0; r < 4; r++) {
        int n = nt + ty + r * 8;
        int k = kt + tx;
        float v = tile[tx][ty + r * 8];
        float h = tf32_hi(v);
        g_Wth[(size_t)n*DIN + k] = h;
        g_Wtl[(size_t)n*DIN + k] = tf32_hi(v - h);
    }
}

// Merged GEMM: g_Call[4096,896] = A @ W^T via tf32 mma.sync on pre-split
// operands. BM=128 BN=64 BK=32, cp.async double-buffered. Blocks with
// n0>=512 (output-critical) use 3x-tf32; n0<512 (mask-only) hi-only.
__global__ __launch_bounds__(256, 2) void sgemm_tc_pipe() {
    extern __shared__ float sm[];
    const int t = threadIdx.x;
    const int lane = t & 31, w = t >> 5;
    const int wm = w >> 1, wn = w & 1;
    const int m0 = blockIdx.y * 128;
    const int n0 = blockIdx.x * 64;
    const bool three = (n0 >= COL_H1);

    const float* AhB = g_Ah + (size_t)m0 * DIN;
    const float* AlB = g_Al + (size_t)m0 * DIN;
    const float* BhB = g_Wth + (size_t)n0 * DIN;
    const float* BlB = g_Wtl + (size_t)n0 * DIN;

    float acc[2][4][4];
#pragma unroll
    for (int mt = 0; mt < 2; mt++)
#pragma unroll
        for (int nt = 0; nt < 4; nt++)
#pragma unroll
            for (int i = 0; i < 4; i++) acc[mt][nt][i] = 0.f;

    auto stage = [&](int kt, int buf) {
        float* base = sm + buf * BUF;
        int kk = kt * 32;
#pragma unroll
        for (int j = 0; j < 4; j++) {
            int idx = t + j * 256;
            int m = idx >> 3, ch = (idx & 7) << 2;
            unsigned d = (unsigned)__cvta_generic_to_shared(base + m * TSTR + ch);
            CP16(d, AhB + (size_t)m * DIN + kk + ch);
        }
#pragma unroll
        for (int j = 0; j < 2; j++) {
            int idx = t + j * 256;
            int n = idx >> 3, ch = (idx & 7) << 2;
            unsigned d = (unsigned)__cvta_generic_to_shared(base + 2*A_TILE + n * TSTR + ch);
            CP16(d, BhB + (size_t)n * DIN + kk + ch);
        }
        if (three) {
#pragma unroll
            for (int j = 0; j < 4; j++) {
                int idx = t + j * 256;
                int m = idx >> 3, ch = (idx & 7) << 2;
                unsigned d = (unsigned)__cvta_generic_to_shared(base + A_TILE + m * TSTR + ch);
                CP16(d, AlB + (size_t)m * DIN + kk + ch);
            }
#pragma unroll
            for (int j = 0; j < 2; j++) {
                int idx = t + j * 256;
                int n = idx >> 3, ch = (idx & 7) << 2;
                unsigned d = (unsigned)__cvta_generic_to_shared(base + 2*A_TILE + B_TILE + n * TSTR + ch);
                CP16(d, BlB + (size_t)n * DIN + kk + ch);
            }
        }
    };

    stage(0, 0);
    CP_COMMIT();
    const int T = DIN / 32;
    for (int kt = 0; kt < T; kt++) {
        int cur = kt & 1;
        if (kt + 1 < T) {
            stage(kt + 1, cur ^ 1);
            CP_COMMIT();
            CP_WAIT1();
        } else {
            CP_WAIT0();
        }
        __syncthreads();
        const unsigned* aH = (const unsigned*)(sm + cur * BUF);
        const unsigned* aL = aH + A_TILE;
        const unsigned* bH = aH + 2*A_TILE;
        const unsigned* bL = bH + B_TILE;
#pragma unroll
        for (int ks = 0; ks < 4; ks++) {
            unsigned ah[2][4], al[2][4], bh[4][2], bl[4][2];
#pragma unroll
            for (int mt = 0; mt < 2; mt++)
#pragma unroll
                for (int i = 0; i < 4; i++) {
                    int m = wm*32 + mt*16 + (lane >> 2) + ((i & 1) << 3);
                    int k = ks*8 + (lane & 3) + ((i >> 1) << 2);
                    ah[mt][i] = aH[m * TSTR + k];
                    if (three) al[mt][i] = aL[m * TSTR + k];
                }
#pragma unroll
            for (int nt = 0; nt < 4; nt++)
#pragma unroll
                for (int i = 0; i < 2; i++) {
                    int n = wn*32 + nt*8 + (lane >> 2);
                    int k = ks*8 + (lane & 3) + (i << 2);
                    bh[nt][i] = bH[n * TSTR + k];
                    if (three) bl[nt][i] = bL[n * TSTR + k];
                }
#pragma unroll
            for (int mt = 0; mt < 2; mt++)
#pragma unroll
                for (int nt = 0; nt < 4; nt++) {
                    MMA_TF32(acc[mt][nt], ah[mt], bh[nt]);
                    if (three) {
                        MMA_TF32(acc[mt][nt], al[mt], bh[nt]);
                        MMA_TF32(acc[mt][nt], ah[mt], bl[nt]);
                    }
                }
        }
        __syncthreads();
    }
#pragma unroll
    for (int mt = 0; mt < 2; mt++)
#pragma unroll
        for (int nt = 0; nt < 4; nt++) {
            int row = m0 + wm*32 + mt*16 + (lane >> 2);
            int col = n0 + wn*32 + nt*8 + ((lane & 3) << 1);
            *(float2*)&g_Call[(size_t)row * WALLP + col] =
                make_float2(acc[mt][nt][0], acc[mt][nt][1]);
            *(float2*)&g_Call[(size_t)(row + 8) * WALLP + col] =
                make_float2(acc[mt][nt][2], acc[mt][nt][3]);
        }
}

// per-row L2 normalize of sim features (adds sim_b); writes tf32-pre-rounded
// values so the gram kernel needs no conversions (rounding there anyway).
__global__ void normalize_kernel(const float* __restrict__ simb) {
    int r = blockIdx.x, tid = threadIdx.x;  // 128 threads
    const float* row = g_Call + (size_t)r * WALLP;
    float ss = 0.f;
    for (int c = tid; c < SD; c += 128) { float v = row[c] + simb[c]; ss += v * v; }
#pragma unroll
    for (int off = 16; off > 0; off >>= 1) ss += __shfl_xor_sync(0xffffffffu, ss, off);
    __shared__ float red[4];
    if ((tid & 31) == 0) red[tid >> 5] = ss;
    __syncthreads();
    float tot = red[0] + red[1] + red[2] + red[3];
    float inv = 1.f / (sqrtf(tot) + 1e-9f);
    for (int c = tid; c < SD; c += 128) {
        float v = row[c] + simb[c];
        g_SF[(size_t)r * SD + c] = tf32_hi(v * inv);
    }
}

__global__ void edge1_kernel(const float* __restrict__ asrc, const float* __restrict__ adst) {
    int n = blockIdx.x * blockDim.x + threadIdx.x;
    if (n >= NODES) return;
    const float* h = g_Call + (size_t)n * WALLP + COL_H1;
    int img = n >> 10;
#pragma unroll
    for (int hh = 0; hh < NH; hh++) {
        float es = 0.f, ed = 0.f;
#pragma unroll
        for (int f = 0; f < NF; f++) {
            float v = h[hh * NF + f];
            es = fmaf(v, asrc[hh * NF + f], es);
            ed = fmaf(v, adst[hh * NF + f], ed);
        }
        g_ES1[n * NH + hh] = es;
        g_ED1[n * NH + hh] = ed;
        atomicMax(&g_M1[img * NH + hh], fenc(es));
    }
}

// IoU edge mask (byte per pair), 16 dsts per block
__global__ void iou_kernel(const float* __restrict__ boxes) {
    __shared__ float4 bx[NN];
    int img = blockIdx.y, tid = threadIdx.x;
    const float4* bsrc = (const float4*)(boxes + (size_t)img * NN * 4);
    for (int i = tid; i < NN; i += 256) bx[i] = bsrc[i];
    __syncthreads();
    unsigned char* M = g_iouM + (size_t)img * NN * NN;
    for (int idx = tid; idx < 16 * NN; idx += 256) {
        int dl = idx >> 10, s = idx & 1023;
        int d = blockIdx.x * 16 + dl;
        float4 A = bx[d], Bb = bx[s];
        float areaA = (A.z - A.x) * (A.w - A.y);
        float areaB = (Bb.z - Bb.x) * (Bb.w - Bb.y);
        float lx = fmaxf(A.x, Bb.x), ly = fmaxf(A.y, Bb.y);
        float rx = fminf(A.z, Bb.z), ry = fminf(A.w, Bb.w);
        float w = fmaxf(rx - lx, 0.f), hh = fmaxf(ry - ly, 0.f);
        float inter = w * hh;
        float iou = inter / (areaA + areaB - inter + 1e-9f);
        M[(size_t)d * NN + s] = (unsigned char)((iou >= 0.4f) || (s == d));
    }
}

// GAT1 aggregation: warp per dst, 8 dsts per block, smem-staged src chunks
__global__ __launch_bounds__(256) void gat1_agg_kernel(const float* __restrict__ b1) {
    int img = blockIdx.y;
    int warp = threadIdx.x >> 5, lane = threadIdx.x & 31;
    int d = blockIdx.x * 8 + warp;
    int gd = img * NN + d;
    __shared__ float sh_h1[128][65];
    __shared__ float sh_es[128][9];
    __shared__ unsigned char sh_m[8][128];
    float acc[64], den[NH], ed[NH], shift[NH];
#pragma unroll
    for (int i = 0; i < 64; i++) acc[i] = 0.f;
#pragma unroll
    for (int h = 0; h < NH; h++) {
        den[h] = 0.f;
        ed[h] = g_ED1[gd * NH + h];
        shift[h] = lrelu(fdec(g_M1[img * NH + h]) + ed[h]);
    }
    for (int c0 = 0; c0 < NN; c0 += 128) {
        __syncthreads();
        for (int i = threadIdx.x; i < 128 * 64; i += 256) {
            int r = i >> 6, c = i & 63;
            sh_h1[r][c] = g_Call[(size_t)(img * NN + c0 + r) * WALLP + COL_H1 + c];
        }
        for (int i = threadIdx.x; i < 128 * 8; i += 256) {
            int r = i >> 3, c = i & 7;
            sh_es[r][c] = g_ES1[(img * NN + c0 + r) * NH + c];
        }
        {
            const unsigned* mrow = (const unsigned*)(g_iouM + (size_t)img * NN * NN + (size_t)d * NN + c0);
            ((unsigned*)sh_m[warp])[lane] = mrow[lane];
        }
        __syncthreads();
        for (int p = 0; p < 4; p++) {
            int sl = p * 32 + lane;
            bool mb = sh_m[warp][sl] != 0;
            if (!__any_sync(0xffffffffu, mb)) continue;
            if (mb) {
#pragma unroll
                for (int h = 0; h < NH; h++) {
                    float w = __expf(lrelu(sh_es[sl][h] + ed[h]) - shift[h]);
                    den[h] += w;
#pragma unroll
                    for (int f = 0; f < NF; f++)
                        acc[h * 8 + f] = fmaf(w, sh_h1[sl][h * 8 + f], acc[h * 8 + f]);
                }
            }
        }
    }
#pragma unroll
    for (int off = 16; off > 0; off >>= 1) {
#pragma unroll
        for (int i = 0; i < 64; i++) acc[i] += __shfl_xor_sync(0xffffffffu, acc[i], off);
#pragma unroll
        for (int h = 0; h < NH; h++) den[h] += __shfl_xor_sync(0xffffffffu, den[h], off);
    }
    if (lane == 0) {
#pragma unroll
        for (int i = 0; i < 64; i++) {
            float v = acc[i] / den[i >> 3] + b1[i];
            g_N1[(size_t)gd * 64 + i] = v > 0.f ? v : expm1f(v);
        }
    }
}

__global__ void gat2_prep_kernel(const float* __restrict__ W2,
                                 const float* __restrict__ asrc2,
                                 const float* __restrict__ adst2) {
    int n = blockIdx.x * blockDim.x + threadIdx.x;
    if (n >= NODES) return;
    int img = n >> 10;
    float x[64];
#pragma unroll
    for (int k = 0; k < 64; k++) x[k] = g_N1[(size_t)n * 64 + k];
    float es = 0.f, ed = 0.f;
    for (int c = 0; c < NC; c++) {
        float a = 0.f;
#pragma unroll
        for (int k = 0; k < 64; k++) a = fmaf(x[k], W2[k * NC + c], a);
        g_H2[n * NC + c] = a;
        es = fmaf(a, asrc2[c], es);
        ed = fmaf(a, adst2[c], ed);
    }
    g_ES2[n] = es;
    g_ED2[n] = ed;
    atomicMax(&g_M2[img], fenc(es));
}

// per-image gram of (pre-rounded tf32) sim features -> byte mask.
// BM=128(s) BN=64(d) BK=32, cp.async double-buffered, no conversions.
__global__ __launch_bounds__(256, 2) void gram_tc_pipe() {
    extern __shared__ float sm[];
    const int img = blockIdx.z;
    const float* SF = g_SF + (size_t)img * NN * SD;
    const int t = threadIdx.x;
    const int lane = t & 31, w = t >> 5;
    const int wm = w >> 1, wn = w & 1;
    const int m0 = blockIdx.y * 128;   // source rows
    const int n0 = blockIdx.x * 64;    // destination rows

    const float* Abase = SF + (size_t)m0 * SD;
    const float* Bbase = SF + (size_t)n0 * SD;

    float acc[2][4][4];
#pragma unroll
    for (int mt = 0; mt < 2; mt++)
#pragma unroll
        for (int nt = 0; nt < 4; nt++)
#pragma unroll
            for (int i = 0; i < 4; i++) acc[mt][nt][i] = 0.f;

    auto stage = [&](int kt, int buf) {
        float* base = sm + buf * (A_TILE + B_TILE);
        int kk = kt * 32;
#pragma unroll
        for (int j = 0; j < 4; j++) {
            int idx = t + j * 256;
            int m = idx >> 3, ch = (idx & 7) << 2;
            unsigned d = (unsigned)__cvta_generic_to_shared(base + m * TSTR + ch);
            CP16(d, Abase + (size_t)m * SD + kk + ch);
        }
#pragma unroll
        for (int j = 0; j < 2; j++) {
            int idx = t + j * 256;
            int n = idx >> 3, ch = (idx & 7) << 2;
            unsigned d = (unsigned)__cvta_generic_to_shared(base + A_TILE + n * TSTR + ch);
            CP16(d, Bbase + (size_t)n * SD + kk + ch);
        }
    };

    stage(0, 0);
    CP_COMMIT();
    const int T = SD / 32;
    for (int kt = 0; kt < T; kt++) {
        int cur = kt & 1;
        if (kt + 1 < T) {
            stage(kt + 1, cur ^ 1);
            CP_COMMIT();
            CP_WAIT1();
        } else {
            CP_WAIT0();
        }
        __syncthreads();
        const unsigned* a_s = (const unsigned*)(sm + cur * (A_TILE + B_TILE));
        const unsigned* b_s = a_s + A_TILE;
#pragma unroll
        for (int ks = 0; ks < 4; ks++) {
            unsigned ah[2][4], bh[4][2];
#pragma unroll
            for (int mt = 0; mt < 2; mt++)
#pragma unroll
                for (int i = 0; i < 4; i++) {
                    int m = wm*32 + mt*16 + (lane >> 2) + ((i & 1) << 3);
                    int k = ks*8 + (lane & 3) + ((i >> 1) << 2);
                    ah[mt][i] = a_s[m * TSTR + k];
                }
#pragma unroll
            for (int nt = 0; nt < 4; nt++)
#pragma unroll
                for (int i = 0; i < 2; i++) {
                    int n = wn*32 + nt*8 + (lane >> 2);
                    int k = ks*8 + (lane & 3) + (i << 2);
                    bh[nt][i] = b_s[n * TSTR + k];
                }
#pragma unroll
            for (int mt = 0; mt < 2; mt++)
#pragma unroll
                for (int nt = 0; nt < 4; nt++)
                    MMA_TF32(acc[mt][nt], ah[mt], bh[nt]);
        }
        __syncthreads();
    }
    unsigned char* M = g_simM + (size_t)img * NN * NN;
#pragma unroll
    for (int mt = 0; mt < 2; mt++)
#pragma unroll
        for (int nt = 0; nt < 4; nt++) {
            int s0 = m0 + wm*32 + mt*16 + (lane >> 2);
            int d0 = n0 + wn*32 + nt*8 + ((lane & 3) << 1);
            M[(size_t)d0 * NN + s0]       = (unsigned char)((acc[mt][nt][0] >= 0.4f) || (s0 == d0));
            M[(size_t)(d0+1) * NN + s0]   = (unsigned char)((acc[mt][nt][1] >= 0.4f) || (s0 == d0+1));
            M[(size_t)d0 * NN + s0+8]     = (unsigned char)((acc[mt][nt][2] >= 0.4f) || (s0+8 == d0));
            M[(size_t)(d0+1) * NN + s0+8] = (unsigned char)((acc[mt][nt][3] >= 0.4f) || (s0+8 == d0+1));
        }
}

__global__ __launch_bounds__(256) void gat2_agg_kernel(const float* __restrict__ b2) {
    int img = blockIdx.y;
    int warp = threadIdx.x >> 5, lane = threadIdx.x & 31;
    int d = blockIdx.x * 8 + warp;
    int gd = img * NN + d;
    __shared__ float sh_h2[128][21];
    __shared__ float sh_es[128];
    __shared__ unsigned char sh_m[8][128];
    float acc[NC], den = 0.f;
#pragma unroll
    for (int c = 0; c < NC; c++) acc[c] = 0.f;
    float ed = g_ED2[gd];
    float shift = lrelu(fdec(g_M2[img]) + ed);
    for (int c0 = 0; c0 < NN; c0 += 128) {
        __syncthreads();
        for (int i = threadIdx.x; i < 128 * NC; i += 256) {
            int r = i / NC, c = i % NC;
            sh_h2[r][c] = g_H2[(img * NN + c0 + r) * NC + c];
        }
        if (threadIdx.x < 128) sh_es[threadIdx.x] = g_ES2[img * NN + c0 + threadIdx.x];
        {
            const unsigned* mrow = (const unsigned*)(g_simM + (size_t)img * NN * NN + (size_t)d * NN + c0);
            ((unsigned*)sh_m[warp])[lane] = mrow[lane];
        }
        __syncthreads();
        for (int p = 0; p < 4; p++) {
            int sl = p * 32 + lane;
            bool mb = sh_m[warp][sl] != 0;
            if (!__any_sync(0xffffffffu, mb)) continue;
            if (mb) {
                float w = __expf(lrelu(sh_es[sl] + ed) - shift);
                den += w;
#pragma unroll
                for (int c = 0; c < NC; c++) acc[c] = fmaf(w, sh_h2[sl][c], acc[c]);
            }
        }
    }
#pragma unroll
    for (int off = 16; off > 0; off >>= 1) {
#pragma unroll
        for (int c = 0; c < NC; c++) acc[c] += __shfl_xor_sync(0xffffffffu, acc[c], off);
        den += __shfl_xor_sync(0xffffffffu, den, off);
    }
    if (lane == 0) {
#pragma unroll
        for (int c = 0; c < NC; c++) g_N2[(size_t)gd * NC + c] = acc[c] / den + b2[c];
    }
}

__global__ void node_kernel(const float* __restrict__ nW, const float* __restrict__ nb,
                            float* __restrict__ out) {
    int n = blockIdx.x * blockDim.x + threadIdx.x;
    if (n >= NODES) return;
    float x[NC], v[NC];
#pragma unroll
    for (int c = 0; c < NC; c++) x[c] = g_N2[(size_t)n * NC + c];
#pragma unroll
    for (int c = 0; c < NC; c++) {
        float a = nb[c];
#pragma unroll
        for (int cc = 0; cc < NC; cc++) a = fmaf(x[cc], nW[cc * NC + c], a);
        v[c] = a;
    }
    float m = v[0];
#pragma unroll
    for (int c = 1; c < NC; c++) m = fmaxf(m, v[c]);
    float s = 0.f;
#pragma unroll
    for (int c = 0; c < NC; c++) { v[c] = __expf(v[c] - m); s += v[c]; }
    float inv = 1.f / s;
#pragma unroll
    for (int c = 0; c < NC; c++) out[OUT_NODE + (size_t)n * NC + c] = v[c] * inv;
}

__global__ void graph_kernel(float* __restrict__ out) {
    int img = blockIdx.x, c = blockIdx.y, tid = threadIdx.x;  // 256 threads
    float s = 0.f;
    for (int node = tid; node < NN; node += 256)
        s += out[OUT_NODE + (size_t)(img * NN + node) * NC + c];
#pragma unroll
    for (int off = 16; off > 0; off >>= 1) s += __shfl_xor_sync(0xffffffffu, s, off);
    __shared__ float red[8];
    if ((tid & 31) == 0) red[tid >> 5] = s;
    __syncthreads();
    if (tid == 0) {
        float tot = 0.f;
#pragma unroll
        for (int i = 0; i < 8; i++) tot += red[i];
        out[img * NC + c] = tot * (1.f / (float)NN);
    }
}

__global__ void scatter_kernel(const float* __restrict__ refb, const float* __restrict__ bboxb,
                               float* __restrict__ out) {
    int idx = blockIdx.x * blockDim.x + threadIdx.x;
    const int REF_TOT = 3 * NODES * NC;       // 245760
    const int BBOX_TOT = 3 * NODES * 80;      // 983040
    if (idx < REF_TOT) {
        int k = idx / (NODES * NC), r = idx % (NODES * NC);
        int n = r / NC, c = r % NC;
        out[OUT_REF + idx] = g_Call[(size_t)n * WALLP + COL_REF + k * NC + c] + refb[k * NC + c];
    } else {
        int j = idx - REF_TOT;
        if (j >= BBOX_TOT) return;
        int k = j / (NODES * 80), r = j % (NODES * 80);
        int n = r / 80, c = r % 80;
        out[OUT_BBOX + j] = g_Call[(size_t)n * WALLP + COL_BBOX + k * 80 + c] + bboxb[k * 80 + c];
    }
}

// ---------------- launch ----------------
extern "C" void kernel_launch(void* const* d_in, const int* in_sizes, int n_in,
                              void* d_out, int out_size) {
    const float* x1     = (const float*)d_in[0];
    const float* boxes  = (const float*)d_in[1];
    const float* simW   = (const float*)d_in[2];
    const float* simb   = (const float*)d_in[3];
    const float* gat1W  = (const float*)d_in[4];
    const float* asrc1  = (const float*)d_in[5];
    const float* adst1  = (const float*)d_in[6];
    const float* b1     = (const float*)d_in[7];
    const float* gat2W  = (const float*)d_in[8];
    const float* asrc2  = (const float*)d_in[9];
    const float* adst2  = (const float*)d_in[10];
    const float* b2     = (const float*)d_in[11];
    const float* nodeW  = (const float*)d_in[12];
    const float* nodeb  = (const float*)d_in[13];
    const float* refW   = (const float*)d_in[14];
    const float* refb   = (const float*)d_in[15];
    const float* bboxW  = (const float*)d_in[16];
    const float* bboxb  = (const float*)d_in[17];
    float* out = (float*)d_out;

    cudaFuncSetAttribute(sgemm_tc_pipe, cudaFuncAttributeMaxDynamicSharedMemorySize, SMEM_BYTES);
    cudaFuncSetAttribute(gram_tc_pipe,  cudaFuncAttributeMaxDynamicSharedMemorySize, 2*(A_TILE+B_TILE)*4);

    init_kernel<<<1, 64>>>();
    splitA_kernel<<<(NODES * DIN / 4 + 255) / 256, 256>>>(x1);
    pack_kernel<<<dim3(WALLP / 32, DIN / 32), dim3(32, 8)>>>(simW, gat1W, refW, bboxW);
    iou_kernel<<<dim3(NN / 16, BI), 256>>>(boxes);
    sgemm_tc_pipe<<<dim3(WALLP / 64, NODES / 128), 256, SMEM_BYTES>>>();
    normalize_kernel<<<NODES, 128>>>(simb);
    edge1_kernel<<<NODES / 256, 256>>>(asrc1, adst1);
    gat1_agg_kernel<<<dim3(NN / 8, BI), 256>>>(b1);
    gat2_prep_kernel<<<NODES / 256, 256>>>(gat2W, asrc2, adst2);
    gram_tc_pipe<<<dim3(NN / 64, NN / 128, BI), 256, 2*(A_TILE+B_TILE)*4>>>();
    gat2_agg_kernel<<<dim3(NN / 8, BI), 256>>>(b2);
    node_kernel<<<NODES / 256, 256>>>(nodeW, nodeb, out);
    graph_kernel<<<dim3(BI, NC), 256>>>(out);
    scatter_kernel<<<(3 * NODES * NC + 3 * NODES * 80 + 255) / 256, 256>>>(refb, bboxb, out);
}

// round 6
// speedup vs baseline: 1.2124x; 1.1499x over previous
#include <cuda_runtime.h>
#include <math.h>

// ---------------- problem constants ----------------
#define BI    4
#define NN    1024
#define DIN   2048
#define SD    512
#define NH    8
#define NF    8
#define NC    20
#define NODES (BI*NN)            // 4096
#define WALLN 876                // 512 sim | 64 gat1 | 60 ref | 240 bbox
#define WALLP 896                // padded to 14*64
#define COL_H1   512
#define COL_REF  576
#define COL_BBOX 636

// output layout (flattened tuple, f32)
#define OUT_NODE  80
#define OUT_REF   82000
#define OUT_BBOX  327760

// ---- sgemm smem: interleaved hi/lo, 72 floats per row (32k x2 + 8 pad) ----
// 72 = 18x16B: m->m+1 shifts banks by 8; conflict-free for LDS.64 fragment
// gathers (half-warp phases) and 16B cp.async stores (8-lane phases).
#define IST 72
#define IA_TILE (128*IST)
#define IB_TILE (64*IST)
#define IBUF (IA_TILE + IB_TILE)
#define SGEMM_SMEM (2*IBUF*4)      // 110592 B, double buffered

// ---- gram smem: hi-only, 36-float stride ----
#define TSTR 36
#define GA_TILE (128*TSTR)
#define GB_TILE (64*TSTR)
#define GRAM_SMEM (2*(GA_TILE+GB_TILE)*4)  // 55296

// sgemm tile-order remap: 14 n-blocks (bx>=8 are 3x-cost), 32 m-blocks
#define NBX 14
#define NBY 32
#define N_THREE (6*NBY)    // 192

// ---------------- scratch (static device memory; no allocs) ----------------
__device__ float g_A2[(size_t)NODES*DIN*2];      // x1 interleaved {hi,lo}
__device__ float g_W2[(size_t)WALLP*DIN*2];      // packed W^T interleaved {hi,lo}
__device__ float g_Call[(size_t)NODES*WALLP];    // packed GEMM out [4096][896]
__device__ float g_SF[NODES*SD];         // normalized sim features (tf32-rounded)
__device__ float g_ES1[NODES*NH];
__device__ float g_ED1[NODES*NH];
__device__ unsigned g_M1[BI*NH];
__device__ float g_N1[NODES*64];         // elu(gat1 out)
__device__ float g_H2[NODES*NC];
__device__ float g_ES2[NODES];
__device__ float g_ED2[NODES];
__device__ unsigned g_M2[BI];
__device__ float g_N2[NODES*NC];
__device__ unsigned char g_simM[(size_t)BI*NN*NN];
__device__ int g_e1[(size_t)NODES*NN];   // IoU edge lists (ascending s)
__device__ int g_e1cnt[NODES];
__device__ int g_e2[(size_t)NODES*NN];   // sim edge lists
__device__ int g_e2cnt[NODES];

// monotonic float<->uint encoding for atomicMax
__device__ __forceinline__ unsigned fenc(float f) {
    unsigned u = __float_as_uint(f);
    return (u & 0x80000000u) ? ~u : (u | 0x80000000u);
}
__device__ __forceinline__ float fdec(unsigned u) {
    u = (u & 0x80000000u) ? (u & 0x7fffffffu) : ~u;
    return __uint_as_float(u);
}
__device__ __forceinline__ float lrelu(float x) { return x > 0.f ? x : 0.2f * x; }

__device__ __forceinline__ unsigned to_tf32(float f) {
    unsigned h; asm("cvt.rna.tf32.f32 %0, %1;" : "=r"(h) : "f"(f));
    return h;
}
__device__ __forceinline__ float tf32_hi(float f) { return __uint_as_float(to_tf32(f)); }

#define MMA_TF32(c, a, b)                                                   \
    asm("mma.sync.aligned.m16n8k8.row.col.f32.tf32.tf32.f32 "               \
        "{%0,%1,%2,%3}, {%4,%5,%6,%7}, {%8,%9}, {%0,%1,%2,%3};"             \
        : "+f"((c)[0]), "+f"((c)[1]), "+f"((c)[2]), "+f"((c)[3])            \
        : "r"((a)[0]), "r"((a)[1]), "r"((a)[2]), "r"((a)[3]),               \
          "r"((b)[0]), "r"((b)[1]))

#define CP16(dst, src)                                                      \
    asm volatile("cp.async.cg.shared.global [%0], [%1], 16;"                \
                 :: "r"(dst), "l"(src))
#define CP_COMMIT() asm volatile("cp.async.commit_group;")
#define CP_WAIT1()  asm volatile("cp.async.wait_group 1;")
#define CP_WAIT0()  asm volatile("cp.async.wait_group 0;")

// ---------------- kernels ----------------
__global__ void init_kernel() {
    int t = threadIdx.x;
    if (t < BI*NH) g_M1[t] = 0u;
    if (t < BI)    g_M2[t] = 0u;
}

// split x1 into interleaved {tf32-hi, tf32-lo} pairs
__global__ void splitA_kernel(const float* __restrict__ A) {
    int i = blockIdx.x * blockDim.x + threadIdx.x;   // float4 index
    float4 v = ((const float4*)A)[i];
    float4 o1, o2;
    o1.x = tf32_hi(v.x); o1.y = tf32_hi(v.x - o1.x);
    o1.z = tf32_hi(v.y); o1.w = tf32_hi(v.y - o1.z);
    o2.x = tf32_hi(v.z); o2.y = tf32_hi(v.z - o2.x);
    o2.z = tf32_hi(v.w); o2.w = tf32_hi(v.w - o2.z);
    ((float4*)g_A2)[2*i]   = o1;
    ((float4*)g_A2)[2*i+1] = o2;
}

// pack weights transposed + split: g_W2[(n*DIN+k)*2 + {0,1}]
__global__ void pack_kernel(const float* __restrict__ simW, const float* __restrict__ gat1W,
                            const float* __restrict__ refW, const float* __restrict__ bboxW) {
    __shared__ float tile[32][33];
    int nt = blockIdx.x * 32, kt = blockIdx.y * 32;
    int tx = threadIdx.x, ty = threadIdx.y;   // 32x8
#pragma unroll
    for (int r = 0; r < 4; r++) {
        int k = kt + ty + r * 8;
        int n = nt + tx;
        float v = 0.f;
        if (n < COL_H1)        v = simW[(size_t)k*SD + n];
        else if (n < COL_REF)  v = gat1W[(size_t)k*64 + (n - COL_H1)];
        else if (n < COL_BBOX) { int jj = n - COL_REF;  int t3 = jj/NC; int c = jj%NC;
                                 v = refW[(size_t)t3*DIN*NC + (size_t)k*NC + c]; }
        else if (n < WALLN)    { int jj = n - COL_BBOX; int t3 = jj/80; int c = jj%80;
                                 v = bboxW[(size_t)t3*DIN*80 + (size_t)k*80 + c]; }
        tile[ty + r * 8][tx] = v;
    }
    __syncthreads();
#pragma unroll
    for (int r = 0; r < 4; r++) {
        int n = nt + ty + r * 8;
        int k = kt + tx;
        float v = tile[tx][ty + r * 8];
        float h = tf32_hi(v);
        g_W2[((size_t)n*DIN + k)*2]     = h;
        g_W2[((size_t)n*DIN + k)*2 + 1] = tf32_hi(v - h);
    }
}

// IoU edges straight to CSR: warp per dst, ballot compaction (ascending s)
__global__ void iou_csr_kernel(const float* __restrict__ boxes) {
    __shared__ float4 bx[NN];
    int img = blockIdx.y, tid = threadIdx.x;
    const float4* bsrc = (const float4*)(boxes + (size_t)img * NN * 4);
    for (int i = tid; i < NN; i += 256) bx[i] = bsrc[i];
    __syncthreads();
    int warp = tid >> 5, lane = tid & 31;
    int d = blockIdx.x * 8 + warp;
    int gd = img * NN + d;
    int* lst = g_e1 + (size_t)gd * NN;
    float4 A = bx[d];
    float areaA = (A.z - A.x) * (A.w - A.y);
    int base = 0;
    for (int p = 0; p < 32; p++) {
        int s = p * 32 + lane;
        float4 Bb = bx[s];
        float areaB = (Bb.z - Bb.x) * (Bb.w - Bb.y);
        float lx = fmaxf(A.x, Bb.x), ly = fmaxf(A.y, Bb.y);
        float rx = fminf(A.z, Bb.z), ry = fminf(A.w, Bb.w);
        float w = fmaxf(rx - lx, 0.f), hh = fmaxf(ry - ly, 0.f);
        float inter = w * hh;
        float iou = inter / (areaA + areaB - inter + 1e-9f);
        bool flag = (iou >= 0.4f) || (s == d);
        unsigned m = __ballot_sync(0xffffffffu, flag);
        if (flag) lst[base + __popc(m & ((1u << lane) - 1u))] = s;
        base += __popc(m);
    }
    if (lane == 0) g_e1cnt[gd] = base;
}

// Merged GEMM with interleaved operands. BM=128 BN=64 BK=32, double-buffered
// cp.async, LDS.64 fragment loads. Linear grid, three-tiles scheduled first.
__global__ __launch_bounds__(256, 2) void sgemm_tc_pipe() {
    extern __shared__ float sm[];
    const int t = threadIdx.x;
    const int lane = t & 31, w = t >> 5;
    const int wm = w >> 1, wn = w & 1;
    int bx, by;
    {
        int b = blockIdx.x;
        if (b < N_THREE) { bx = 8 + b % 6; by = b / 6; }
        else             { int r = b - N_THREE; bx = r & 7; by = r >> 3; }
    }
    const int m0 = by * 128;
    const int n0 = bx * 64;
    const bool three = (n0 >= COL_H1);

    const float* Abase = g_A2 + (size_t)m0 * DIN * 2;
    const float* Bbase = g_W2 + (size_t)n0 * DIN * 2;

    float acc[2][4][4];
#pragma unroll
    for (int mt = 0; mt < 2; mt++)
#pragma unroll
        for (int nt = 0; nt < 4; nt++)
#pragma unroll
            for (int i = 0; i < 4; i++) acc[mt][nt][i] = 0.f;

    auto stage = [&](int kt, int buf) {
        float* base = sm + buf * IBUF;
        int koff = kt * 64;                  // float offset within interleaved row
#pragma unroll
        for (int j = 0; j < 8; j++) {
            int idx = t + j * 256;
            int m = idx >> 4, ch = (idx & 15) << 2;
            unsigned d = (unsigned)__cvta_generic_to_shared(base + m * IST + ch);
            CP16(d, Abase + (size_t)m * DIN * 2 + koff + ch);
        }
#pragma unroll
        for (int j = 0; j < 4; j++) {
            int idx = t + j * 256;
            int n = idx >> 4, ch = (idx & 15) << 2;
            unsigned d = (unsigned)__cvta_generic_to_shared(base + IA_TILE + n * IST + ch);
            CP16(d, Bbase + (size_t)n * DIN * 2 + koff + ch);
        }
    };

    stage(0, 0);
    CP_COMMIT();
    const int T = DIN / 32;
    for (int kt = 0; kt < T; kt++) {
        int cur = kt & 1;
        if (kt + 1 < T) {
            stage(kt + 1, cur ^ 1);
            CP_COMMIT();
            CP_WAIT1();
        } else {
            CP_WAIT0();
        }
        __syncthreads();
        const float2* aS = (const float2*)(sm + cur * IBUF);              // [m][36]
        const float2* bS = (const float2*)(sm + cur * IBUF + IA_TILE);    // [n][36]
#pragma unroll
        for (int ks = 0; ks < 4; ks++) {
            unsigned ah[2][4], al[2][4], bh[4][2], bl[4][2];
#pragma unroll
            for (int mt = 0; mt < 2; mt++)
#pragma unroll
                for (int im = 0; im < 2; im++)
#pragma unroll
                    for (int ik = 0; ik < 2; ik++) {
                        int m = wm*32 + mt*16 + (lane >> 2) + (im << 3);
                        int k = ks*8 + (lane & 3) + (ik << 2);
                        float2 v = aS[m * 36 + k];
                        int i = im + (ik << 1);
                        ah[mt][i] = __float_as_uint(v.x);
                        al[mt][i] = __float_as_uint(v.y);
                    }
#pragma unroll
            for (int nt = 0; nt < 4; nt++)
#pragma unroll
                for (int ik = 0; ik < 2; ik++) {
                    int n = wn*32 + nt*8 + (lane >> 2);
                    int k = ks*8 + (lane & 3) + (ik << 2);
                    float2 v = bS[n * 36 + k];
                    bh[nt][ik] = __float_as_uint(v.x);
                    bl[nt][ik] = __float_as_uint(v.y);
                }
#pragma unroll
            for (int mt = 0; mt < 2; mt++)
#pragma unroll
                for (int nt = 0; nt < 4; nt++) {
                    MMA_TF32(acc[mt][nt], ah[mt], bh[nt]);
                    if (three) {
                        MMA_TF32(acc[mt][nt], al[mt], bh[nt]);
                        MMA_TF32(acc[mt][nt], ah[mt], bl[nt]);
                    }
                }
        }
        __syncthreads();
    }
#pragma unroll
    for (int mt = 0; mt < 2; mt++)
#pragma unroll
        for (int nt = 0; nt < 4; nt++) {
            int row = m0 + wm*32 + mt*16 + (lane >> 2);
            int col = n0 + wn*32 + nt*8 + ((lane & 3) << 1);
            *(float2*)&g_Call[(size_t)row * WALLP + col] =
                make_float2(acc[mt][nt][0], acc[mt][nt][1]);
            *(float2*)&g_Call[(size_t)(row + 8) * WALLP + col] =
                make_float2(acc[mt][nt][2], acc[mt][nt][3]);
        }
}

// per-row L2 normalize of sim features (adds sim_b), writes tf32-pre-rounded
__global__ void normalize_kernel(const float* __restrict__ simb) {
    int r = blockIdx.x, tid = threadIdx.x;  // 128 threads
    const float* row = g_Call + (size_t)r * WALLP;
    float ss = 0.f;
    for (int c = tid; c < SD; c += 128) { float v = row[c] + simb[c]; ss += v * v; }
#pragma unroll
    for (int off = 16; off > 0; off >>= 1) ss += __shfl_xor_sync(0xffffffffu, ss, off);
    __shared__ float red[4];
    if ((tid & 31) == 0) red[tid >> 5] = ss;
    __syncthreads();
    float tot = red[0] + red[1] + red[2] + red[3];
    float inv = 1.f / (sqrtf(tot) + 1e-9f);
    for (int c = tid; c < SD; c += 128) {
        float v = row[c] + simb[c];
        g_SF[(size_t)r * SD + c] = tf32_hi(v * inv);
    }
}

__global__ void edge1_kernel(const float* __restrict__ asrc, const float* __restrict__ adst) {
    int n = blockIdx.x * blockDim.x + threadIdx.x;
    if (n >= NODES) return;
    const float* h = g_Call + (size_t)n * WALLP + COL_H1;
    int img = n >> 10;
#pragma unroll
    for (int hh = 0; hh < NH; hh++) {
        float es = 0.f, ed = 0.f;
#pragma unroll
        for (int f = 0; f < NF; f++) {
            float v = h[hh * NF + f];
            es = fmaf(v, asrc[hh * NF + f], es);
            ed = fmaf(v, adst[hh * NF + f], ed);
        }
        g_ES1[n * NH + hh] = es;
        g_ED1[n * NH + hh] = ed;
        atomicMax(&g_M1[img * NH + hh], fenc(es));
    }
}

// GAT1 aggregation via CSR: block(64) per dst, thread = channel
__global__ void gat1_agg_csr(const float* __restrict__ b1) {
    int gd = blockIdx.x;
    int img = gd >> 10;
    int c = threadIdx.x;         // 0..63
    int h = c >> 3;
    float ed = g_ED1[gd * NH + h];
    float shift = lrelu(fdec(g_M1[img * NH + h]) + ed);
    int cnt = g_e1cnt[gd];
    const int* lst = g_e1 + (size_t)gd * NN;
    float acc = 0.f, den = 0.f;
    for (int e = 0; e < cnt; e++) {
        int s = lst[e];
        int gs = (img << 10) + s;
        float es = g_ES1[gs * NH + h];
        float w = __expf(lrelu(es + ed) - shift);
        den += w;
        acc = fmaf(w, g_Call[(size_t)gs * WALLP + COL_H1 + c], acc);
    }
    float v = acc / den + b1[c];
    g_N1[(size_t)gd * 64 + c] = v > 0.f ? v : expm1f(v);
}

__global__ void gat2_prep_kernel(const float* __restrict__ W2,
                                 const float* __restrict__ asrc2,
                                 const float* __restrict__ adst2) {
    int n = blockIdx.x * blockDim.x + threadIdx.x;
    if (n >= NODES) return;
    int img = n >> 10;
    float x[64];
#pragma unroll
    for (int k = 0; k < 64; k++) x[k] = g_N1[(size_t)n * 64 + k];
    float es = 0.f, ed = 0.f;
    for (int c = 0; c < NC; c++) {
        float a = 0.f;
#pragma unroll
        for (int k = 0; k < 64; k++) a = fmaf(x[k], W2[k * NC + c], a);
        g_H2[n * NC + c] = a;
        es = fmaf(a, asrc2[c], es);
        ed = fmaf(a, adst2[c], ed);
    }
    g_ES2[n] = es;
    g_ED2[n] = ed;
    atomicMax(&g_M2[img], fenc(es));
}

// per-image gram of (pre-rounded tf32) sim features -> byte mask
__global__ __launch_bounds__(256, 2) void gram_tc_pipe() {
    extern __shared__ float sm[];
    const int img = blockIdx.z;
    const float* SF = g_SF + (size_t)img * NN * SD;
    const int t = threadIdx.x;
    const int lane = t & 31, w = t >> 5;
    const int wm = w >> 1, wn = w & 1;
    const int m0 = blockIdx.y * 128;
    const int n0 = blockIdx.x * 64;

    const float* Abase = SF + (size_t)m0 * SD;
    const float* Bbase = SF + (size_t)n0 * SD;

    float acc[2][4][4];
#pragma unroll
    for (int mt = 0; mt < 2; mt++)
#pragma unroll
        for (int nt = 0; nt < 4; nt++)
#pragma unroll
            for (int i = 0; i < 4; i++) acc[mt][nt][i] = 0.f;

    auto stage = [&](int kt, int buf) {
        float* base = sm + buf * (GA_TILE + GB_TILE);
        int kk = kt * 32;
#pragma unroll
        for (int j = 0; j < 4; j++) {
            int idx = t + j * 256;
            int m = idx >> 3, ch = (idx & 7) << 2;
            unsigned d = (unsigned)__cvta_generic_to_shared(base + m * TSTR + ch);
            CP16(d, Abase + (size_t)m * SD + kk + ch);
        }
#pragma unroll
        for (int j = 0; j < 2; j++) {
            int idx = t + j * 256;
            int n = idx >> 3, ch = (idx & 7) << 2;
            unsigned d = (unsigned)__cvta_generic_to_shared(base + GA_TILE + n * TSTR + ch);
            CP16(d, Bbase + (size_t)n * SD + kk + ch);
        }
    };

    stage(0, 0);
    CP_COMMIT();
    const int T = SD / 32;
    for (int kt = 0; kt < T; kt++) {
        int cur = kt & 1;
        if (kt + 1 < T) {
            stage(kt + 1, cur ^ 1);
            CP_COMMIT();
            CP_WAIT1();
        } else {
            CP_WAIT0();
        }
        __syncthreads();
        const unsigned* a_s = (const unsigned*)(sm + cur * (GA_TILE + GB_TILE));
        const unsigned* b_s = a_s + GA_TILE;
#pragma unroll
        for (int ks = 0; ks < 4; ks++) {
            unsigned ah[2][4], bh[4][2];
#pragma unroll
            for (int mt = 0; mt < 2; mt++)
#pragma unroll
                for (int i = 0; i < 4; i++) {
                    int m = wm*32 + mt*16 + (lane >> 2) + ((i & 1) << 3);
                    int k = ks*8 + (lane & 3) + ((i >> 1) << 2);
                    ah[mt][i] = a_s[m * TSTR + k];
                }
#pragma unroll
            for (int nt = 0; nt < 4; nt++)
#pragma unroll
                for (int i = 0; i < 2; i++) {
                    int n = wn*32 + nt*8 + (lane >> 2);
                    int k = ks*8 + (lane & 3) + (i << 2);
                    bh[nt][i] = b_s[n * TSTR + k];
                }
#pragma unroll
            for (int mt = 0; mt < 2; mt++)
#pragma unroll
                for (int nt = 0; nt < 4; nt++)
                    MMA_TF32(acc[mt][nt], ah[mt], bh[nt]);
        }
        __syncthreads();
    }
    unsigned char* M = g_simM + (size_t)img * NN * NN;
#pragma unroll
    for (int mt = 0; mt < 2; mt++)
#pragma unroll
        for (int nt = 0; nt < 4; nt++) {
            int s0 = m0 + wm*32 + mt*16 + (lane >> 2);
            int d0 = n0 + wn*32 + nt*8 + ((lane & 3) << 1);
            M[(size_t)d0 * NN + s0]       = (unsigned char)((acc[mt][nt][0] >= 0.4f) || (s0 == d0));
            M[(size_t)(d0+1) * NN + s0]   = (unsigned char)((acc[mt][nt][1] >= 0.4f) || (s0 == d0+1));
            M[(size_t)d0 * NN + s0+8]     = (unsigned char)((acc[mt][nt][2] >= 0.4f) || (s0+8 == d0));
            M[(size_t)(d0+1) * NN + s0+8] = (unsigned char)((acc[mt][nt][3] >= 0.4f) || (s0+8 == d0+1));
        }
}

// compact sim byte mask to CSR: warp per dst (ascending s)
__global__ void sim_csr_kernel() {
    int img = blockIdx.y, tid = threadIdx.x;
    int warp = tid >> 5, lane = tid & 31;
    int d = blockIdx.x * 8 + warp;
    int gd = img * NN + d;
    const unsigned char* M = g_simM + (size_t)img * NN * NN + (size_t)d * NN;
    int* lst = g_e2 + (size_t)gd * NN;
    int base = 0;
    for (int p = 0; p < 32; p++) {
        int s = p * 32 + lane;
        bool flag = M[s] != 0;
        unsigned m = __ballot_sync(0xffffffffu, flag);
        if (flag) lst[base + __popc(m & ((1u << lane) - 1u))] = s;
        base += __popc(m);
    }
    if (lane == 0) g_e2cnt[gd] = base;
}

// GAT2 aggregation via CSR: block(32) per dst
__global__ void gat2_agg_csr(const float* __restrict__ b2) {
    int gd = blockIdx.x;
    int img = gd >> 10;
    int c = threadIdx.x;         // 0..31, active c<NC
    float ed = g_ED2[gd];
    float shift = lrelu(fdec(g_M2[img]) + ed);
    int cnt = g_e2cnt[gd];
    const int* lst = g_e2 + (size_t)gd * NN;
    float acc = 0.f, den = 0.f;
    for (int e = 0; e < cnt; e++) {
        int s = lst[e];
        int gs = (img << 10) + s;
        float es = g_ES2[gs];
        float w = __expf(lrelu(es + ed) - shift);
        den += w;
        if (c < NC) acc = fmaf(w, g_H2[gs * NC + c], acc);
    }
    if (c < NC) g_N2[(size_t)gd * NC + c] = acc / den + b2[c];
}

__global__ void node_kernel(const float* __restrict__ nW, const float* __restrict__ nb,
                            float* __restrict__ out) {
    int n = blockIdx.x * blockDim.x + threadIdx.x;
    if (n >= NODES) return;
    float x[NC], v[NC];
#pragma unroll
    for (int c = 0; c < NC; c++) x[c] = g_N2[(size_t)n * NC + c];
#pragma unroll
    for (int c = 0; c < NC; c++) {
        float a = nb[c];
#pragma unroll
        for (int cc = 0; cc < NC; cc++) a = fmaf(x[cc], nW[cc * NC + c], a);
        v[c] = a;
    }
    float m = v[0];
#pragma unroll
    for (int c = 1; c < NC; c++) m = fmaxf(m, v[c]);
    float s = 0.f;
#pragma unroll
    for (int c = 0; c < NC; c++) { v[c] = __expf(v[c] - m); s += v[c]; }
    float inv = 1.f / s;
#pragma unroll
    for (int c = 0; c < NC; c++) out[OUT_NODE + (size_t)n * NC + c] = v[c] * inv;
}

__global__ void graph_kernel(float* __restrict__ out) {
    int img = blockIdx.x, c = blockIdx.y, tid = threadIdx.x;  // 256 threads
    float s = 0.f;
    for (int node = tid; node < NN; node += 256)
        s += out[OUT_NODE + (size_t)(img * NN + node) * NC + c];
#pragma unroll
    for (int off = 16; off > 0; off >>= 1) s += __shfl_xor_sync(0xffffffffu, s, off);
    __shared__ float red[8];
    if ((tid & 31) == 0) red[tid >> 5] = s;
    __syncthreads();
    if (tid == 0) {
        float tot = 0.f;
#pragma unroll
        for (int i = 0; i < 8; i++) tot += red[i];
        out[img * NC + c] = tot * (1.f / (float)NN);
    }
}

__global__ void scatter_kernel(const float* __restrict__ refb, const float* __restrict__ bboxb,
                               float* __restrict__ out) {
    int idx = blockIdx.x * blockDim.x + threadIdx.x;
    const int REF_TOT = 3 * NODES * NC;       // 245760
    const int BBOX_TOT = 3 * NODES * 80;      // 983040
    if (idx < REF_TOT) {
        int k = idx / (NODES * NC), r = idx % (NODES * NC);
        int n = r / NC, c = r % NC;
        out[OUT_REF + idx] = g_Call[(size_t)n * WALLP + COL_REF + k * NC + c] + refb[k * NC + c];
    } else {
        int j = idx - REF_TOT;
        if (j >= BBOX_TOT) return;
        int k = j / (NODES * 80), r = j % (NODES * 80);
        int n = r / 80, c = r % 80;
        out[OUT_BBOX + j] = g_Call[(size_t)n * WALLP + COL_BBOX + k * 80 + c] + bboxb[k * 80 + c];
    }
}

// ---------------- launch ----------------
extern "C" void kernel_launch(void* const* d_in, const int* in_sizes, int n_in,
                              void* d_out, int out_size) {
    const float* x1     = (const float*)d_in[0];
    const float* boxes  = (const float*)d_in[1];
    const float* simW   = (const float*)d_in[2];
    const float* simb   = (const float*)d_in[3];
    const float* gat1W  = (const float*)d_in[4];
    const float* asrc1  = (const float*)d_in[5];
    const float* adst1  = (const float*)d_in[6];
    const float* b1     = (const float*)d_in[7];
    const float* gat2W  = (const float*)d_in[8];
    const float* asrc2  = (const float*)d_in[9];
    const float* adst2  = (const float*)d_in[10];
    const float* b2     = (const float*)d_in[11];
    const float* nodeW  = (const float*)d_in[12];
    const float* nodeb  = (const float*)d_in[13];
    const float* refW   = (const float*)d_in[14];
    const float* refb   = (const float*)d_in[15];
    const float* bboxW  = (const float*)d_in[16];
    const float* bboxb  = (const float*)d_in[17];
    float* out = (float*)d_out;

    cudaFuncSetAttribute(sgemm_tc_pipe, cudaFuncAttributeMaxDynamicSharedMemorySize, SGEMM_SMEM);
    cudaFuncSetAttribute(gram_tc_pipe,  cudaFuncAttributeMaxDynamicSharedMemorySize, GRAM_SMEM);

    init_kernel<<<1, 64>>>();
    splitA_kernel<<<(NODES * DIN / 4 + 255) / 256, 256>>>(x1);
    pack_kernel<<<dim3(WALLP / 32, DIN / 32), dim3(32, 8)>>>(simW, gat1W, refW, bboxW);
    iou_csr_kernel<<<dim3(NN / 8, BI), 256>>>(boxes);
    sgemm_tc_pipe<<<NBX * NBY, 256, SGEMM_SMEM>>>();
    normalize_kernel<<<NODES, 128>>>(simb);
    edge1_kernel<<<NODES / 256, 256>>>(asrc1, adst1);
    gat1_agg_csr<<<NODES, 64>>>(b1);
    gat2_prep_kernel<<<NODES / 256, 256>>>(gat2W, asrc2, adst2);
    gram_tc_pipe<<<dim3(NN / 64, NN / 128, BI), 256, GRAM_SMEM>>>();
    sim_csr_kernel<<<dim3(NN / 8, BI), 256>>>();
    gat2_agg_csr<<<NODES, 32>>>(b2);
    node_kernel<<<NODES / 256, 256>>>(nodeW, nodeb, out);
    graph_kernel<<<dim3(BI, NC), 256>>>(out);
    scatter_kernel<<<(3 * NODES * NC + 3 * NODES * 80 + 255) / 256, 256>>>(refb, bboxb, out);
}

// round 7
// speedup vs baseline: 2.1685x; 1.7886x over previous
#include <cuda_runtime.h>
#include <cuda_bf16.h>
#include <math.h>

// ---------------- problem constants ----------------
#define BI    4
#define NN    1024
#define DIN   2048
#define SD    512
#define NH    8
#define NF    8
#define NC    20
#define NODES (BI*NN)            // 4096
#define WALLN 876                // 512 sim | 64 gat1 | 60 ref | 240 bbox
#define WALLP 896
#define COL_H1   512
#define COL_REF  576
#define COL_BBOX 636

// output layout (flattened tuple, f32)
#define OUT_NODE  80
#define OUT_REF   82000
#define OUT_BBOX  327760

// ---- sgemm smem: bf16 planes, 64B per 32-k row, XOR-swizzled chunks ----
#define ATB 8192                  // 128 rows * 64B
#define BTB 4096                  // 64 rows * 64B
#define BUFB (2*ATB + 2*BTB)      // Ah, Al, Bh, Bl = 24576
#define SGEMM_SMEM (2*BUFB)       // 49152, double buffered
#define GBUFB (ATB + BTB)         // gram: hi only = 12288
#define GRAM_SMEM (2*GBUFB)       // 24576

// sgemm tile-order remap: 14 n-blocks (bx>=8 are 3-product), 32 m-blocks
#define NBX 14
#define NBY 32
#define N_THREE (6*NBY)    // 192

// ---------------- scratch (static device memory; no allocs) ----------------
__device__ __nv_bfloat16 g_Ah[(size_t)NODES*DIN];   // x1 hi (k-permuted)
__device__ __nv_bfloat16 g_Al[(size_t)NODES*DIN];   // x1 lo
__device__ __nv_bfloat16 g_Wh[(size_t)WALLP*DIN];   // W^T hi (k-permuted)
__device__ __nv_bfloat16 g_Wl[(size_t)WALLP*DIN];   // W^T lo
__device__ float g_Call[(size_t)NODES*WALLP];       // GEMM out [4096][896] f32
__device__ __nv_bfloat16 g_SFb[(size_t)NODES*SD];   // normalized sim feats (bf16, permuted)
__device__ float g_ES1[NODES*NH];
__device__ float g_ED1[NODES*NH];
__device__ unsigned g_M1[BI*NH];
__device__ float g_N1[NODES*64];
__device__ float g_H2[NODES*NC];
__device__ float g_ES2[NODES];
__device__ float g_ED2[NODES];
__device__ unsigned g_M2[BI];
__device__ float g_N2[NODES*NC];
__device__ unsigned char g_simM[(size_t)BI*NN*NN];
__device__ int g_e1[(size_t)NODES*NN];
__device__ int g_e1cnt[NODES];
__device__ int g_e2[(size_t)NODES*NN];
__device__ int g_e2cnt[NODES];

// monotonic float<->uint encoding for atomicMax
__device__ __forceinline__ unsigned fenc(float f) {
    unsigned u = __float_as_uint(f);
    return (u & 0x80000000u) ? ~u : (u | 0x80000000u);
}
__device__ __forceinline__ float fdec(unsigned u) {
    u = (u & 0x80000000u) ? (u & 0x7fffffffu) : ~u;
    return __uint_as_float(u);
}
__device__ __forceinline__ float lrelu(float x) { return x > 0.f ? x : 0.2f * x; }

// k-permutation within each 16-group: fragment quads {k,k+1,k+8,k+9} contiguous
__device__ __forceinline__ int kperm(int r) {
    return ((r & 6) << 1) | (r & 1) | ((r & 8) >> 2);
}

#define MMA_BF16(c, a, b)                                                   \
    asm("mma.sync.aligned.m16n8k16.row.col.f32.bf16.bf16.f32 "              \
        "{%0,%1,%2,%3}, {%4,%5,%6,%7}, {%8,%9}, {%0,%1,%2,%3};"             \
        : "+f"((c)[0]), "+f"((c)[1]), "+f"((c)[2]), "+f"((c)[3])            \
        : "r"((a)[0]), "r"((a)[1]), "r"((a)[2]), "r"((a)[3]),               \
          "r"((b)[0]), "r"((b)[1]))

#define CP16(dst, src)                                                      \
    asm volatile("cp.async.cg.shared.global [%0], [%1], 16;"                \
                 :: "r"(dst), "l"(src))
#define CP_COMMIT() asm volatile("cp.async.commit_group;")
#define CP_WAIT1()  asm volatile("cp.async.wait_group 1;")
#define CP_WAIT0()  asm volatile("cp.async.wait_group 0;")

// ---------------- kernels ----------------

// split x1 into bf16 hi/lo planes, k-permuted; thread per 16-element group
__global__ void splitA_kernel(const float* __restrict__ A) {
    size_t idx = (size_t)blockIdx.x * blockDim.x + threadIdx.x;  // group index
    const float4* s4 = (const float4*)(A + idx * 16);
    float v[16];
#pragma unroll
    for (int i = 0; i < 4; i++) {
        float4 q = s4[i];
        v[i*4+0] = q.x; v[i*4+1] = q.y; v[i*4+2] = q.z; v[i*4+3] = q.w;
    }
    __nv_bfloat16 hb[16], lb[16];
#pragma unroll
    for (int r = 0; r < 16; r++) {
        __nv_bfloat16 h = __float2bfloat16_rn(v[r]);
        __nv_bfloat16 l = __float2bfloat16_rn(v[r] - __bfloat162float(h));
        int j = kperm(r);
        hb[j] = h; lb[j] = l;
    }
    ((uint4*)(g_Ah + idx * 16))[0] = ((uint4*)hb)[0];
    ((uint4*)(g_Ah + idx * 16))[1] = ((uint4*)hb)[1];
    ((uint4*)(g_Al + idx * 16))[0] = ((uint4*)lb)[0];
    ((uint4*)(g_Al + idx * 16))[1] = ((uint4*)lb)[1];
}

// pack weights transposed + bf16 split + k-permute; also zero M1/M2
__global__ void pack_kernel(const float* __restrict__ simW, const float* __restrict__ gat1W,
                            const float* __restrict__ refW, const float* __restrict__ bboxW) {
    __shared__ float tile[32][33];
    int nt = blockIdx.x * 32, kt = blockIdx.y * 32;
    int tx = threadIdx.x, ty = threadIdx.y;   // 32x8
    if (blockIdx.x == 0 && blockIdx.y == 0 && ty == 0) {
        if (tx < BI*NH) g_M1[tx] = 0u;
        if (tx < BI)    g_M2[tx] = 0u;
    }
#pragma unroll
    for (int r = 0; r < 4; r++) {
        int k = kt + ty + r * 8;
        int n = nt + tx;
        float v = 0.f;
        if (n < COL_H1)        v = simW[(size_t)k*SD + n];
        else if (n < COL_REF)  v = gat1W[(size_t)k*64 + (n - COL_H1)];
        else if (n < COL_BBOX) { int jj = n - COL_REF;  int t3 = jj/NC; int c = jj%NC;
                                 v = refW[(size_t)t3*DIN*NC + (size_t)k*NC + c]; }
        else if (n < WALLN)    { int jj = n - COL_BBOX; int t3 = jj/80; int c = jj%80;
                                 v = bboxW[(size_t)t3*DIN*80 + (size_t)k*80 + c]; }
        tile[ty + r * 8][tx] = v;
    }
    __syncthreads();
#pragma unroll
    for (int r = 0; r < 4; r++) {
        int n = nt + ty + r * 8;
        int k = kt + tx;
        int kp = (k & ~15) | kperm(k & 15);
        float v = tile[tx][ty + r * 8];
        __nv_bfloat16 h = __float2bfloat16_rn(v);
        g_Wh[(size_t)n*DIN + kp] = h;
        g_Wl[(size_t)n*DIN + kp] = __float2bfloat16_rn(v - __bfloat162float(h));
    }
}

// IoU edges straight to CSR: warp per dst, ballot compaction (ascending s)
__global__ void iou_csr_kernel(const float* __restrict__ boxes) {
    __shared__ float4 bx[NN];
    int img = blockIdx.y, tid = threadIdx.x;
    const float4* bsrc = (const float4*)(boxes + (size_t)img * NN * 4);
    for (int i = tid; i < NN; i += 256) bx[i] = bsrc[i];
    __syncthreads();
    int warp = tid >> 5, lane = tid & 31;
    int d = blockIdx.x * 8 + warp;
    int gd = img * NN + d;
    int* lst = g_e1 + (size_t)gd * NN;
    float4 A = bx[d];
    float areaA = (A.z - A.x) * (A.w - A.y);
    int base = 0;
    for (int p = 0; p < 32; p++) {
        int s = p * 32 + lane;
        float4 Bb = bx[s];
        float areaB = (Bb.z - Bb.x) * (Bb.w - Bb.y);
        float lx = fmaxf(A.x, Bb.x), ly = fmaxf(A.y, Bb.y);
        float rx = fminf(A.z, Bb.z), ry = fminf(A.w, Bb.w);
        float w = fmaxf(rx - lx, 0.f), hh = fmaxf(ry - ly, 0.f);
        float inter = w * hh;
        float iou = inter / (areaA + areaB - inter + 1e-9f);
        bool flag = (iou >= 0.4f) || (s == d);
        unsigned m = __ballot_sync(0xffffffffu, flag);
        if (flag) lst[base + __popc(m & ((1u << lane) - 1u))] = s;
        base += __popc(m);
    }
    if (lane == 0) g_e1cnt[gd] = base;
}

// Merged GEMM: bf16 m16n8k16 on pre-split permuted planes. BM=128 BN=64
// BK=32, double-buffered cp.async, LDS.64 fragments via XOR chunk swizzle.
__global__ __launch_bounds__(256, 2) void sgemm_tc_pipe() {
    extern __shared__ char smem[];
    const int t = threadIdx.x;
    const int lane = t & 31, w = t >> 5;
    const int wm = w >> 1, wn = w & 1;
    int bx, by;
    {
        int b = blockIdx.x;
        if (b < N_THREE) { bx = 8 + b % 6; by = b / 6; }
        else             { int r = b - N_THREE; bx = r & 7; by = r >> 3; }
    }
    const int m0 = by * 128;
    const int n0 = bx * 64;
    const bool three = (n0 >= COL_H1);

    const char* AhB = (const char*)(g_Ah + (size_t)m0 * DIN);
    const char* AlB = (const char*)(g_Al + (size_t)m0 * DIN);
    const char* BhB = (const char*)(g_Wh + (size_t)n0 * DIN);
    const char* BlB = (const char*)(g_Wl + (size_t)n0 * DIN);

    float acc[2][4][4];
#pragma unroll
    for (int mt = 0; mt < 2; mt++)
#pragma unroll
        for (int nt = 0; nt < 4; nt++)
#pragma unroll
            for (int i = 0; i < 4; i++) acc[mt][nt][i] = 0.f;

    auto stage = [&](int kt, int buf) {
        char* base = smem + buf * BUFB;
        size_t koff = (size_t)kt * 64;     // bytes within a row (32 bf16)
#pragma unroll
        for (int j = 0; j < 2; j++) {
            int idx = t + j * 256;
            int m = idx >> 2, c = idx & 3;
            int doff = m * 64 + ((c ^ (m & 3)) << 4);
            const char* sA = AhB + (size_t)m * DIN * 2 + koff + c * 16;
            CP16((unsigned)__cvta_generic_to_shared(base + doff), sA);
        }
        {
            int n = t >> 2, c = t & 3;
            int doff = n * 64 + ((c ^ (n & 3)) << 4);
            CP16((unsigned)__cvta_generic_to_shared(base + 2*ATB + doff),
                 BhB + (size_t)n * DIN * 2 + koff + c * 16);
        }
        if (three) {
#pragma unroll
            for (int j = 0; j < 2; j++) {
                int idx = t + j * 256;
                int m = idx >> 2, c = idx & 3;
                int doff = m * 64 + ((c ^ (m & 3)) << 4);
                CP16((unsigned)__cvta_generic_to_shared(base + ATB + doff),
                     AlB + (size_t)m * DIN * 2 + koff + c * 16);
            }
            {
                int n = t >> 2, c = t & 3;
                int doff = n * 64 + ((c ^ (n & 3)) << 4);
                CP16((unsigned)__cvta_generic_to_shared(base + 2*ATB + BTB + doff),
                     BlB + (size_t)n * DIN * 2 + koff + c * 16);
            }
        }
    };

    stage(0, 0);
    CP_COMMIT();
    const int T = DIN / 32;
    const int q = lane & 3, g = lane >> 2;
    for (int kt = 0; kt < T; kt++) {
        int cur = kt & 1;
        if (kt + 1 < T) {
            stage(kt + 1, cur ^ 1);
            CP_COMMIT();
            CP_WAIT1();
        } else {
            CP_WAIT0();
        }
        __syncthreads();
        const char* AhS = smem + cur * BUFB;
        const char* AlS = AhS + ATB;
        const char* BhS = AhS + 2*ATB;
        const char* BlS = BhS + BTB;
#pragma unroll
        for (int s = 0; s < 2; s++) {
            unsigned ah[2][4], al[2][4], bh[4][2], bl[4][2];
            int sc = (s << 1) | (q >> 1);
            int hb = (q & 1) << 3;
#pragma unroll
            for (int mt = 0; mt < 2; mt++) {
                int r0 = wm*32 + mt*16 + g;
                int off0 = r0 * 64 + ((sc ^ (r0 & 3)) << 4) + hb;
                uint2 v0 = *(const uint2*)(AhS + off0);
                uint2 v1 = *(const uint2*)(AhS + off0 + 512);
                ah[mt][0] = v0.x; ah[mt][1] = v1.x; ah[mt][2] = v0.y; ah[mt][3] = v1.y;
                if (three) {
                    uint2 u0 = *(const uint2*)(AlS + off0);
                    uint2 u1 = *(const uint2*)(AlS + off0 + 512);
                    al[mt][0] = u0.x; al[mt][1] = u1.x; al[mt][2] = u0.y; al[mt][3] = u1.y;
                }
            }
#pragma unroll
            for (int nt = 0; nt < 4; nt++) {
                int n = wn*32 + nt*8 + g;
                int off = n * 64 + ((sc ^ (n & 3)) << 4) + hb;
                uint2 vb = *(const uint2*)(BhS + off);
                bh[nt][0] = vb.x; bh[nt][1] = vb.y;
                if (three) {
                    uint2 ub = *(const uint2*)(BlS + off);
                    bl[nt][0] = ub.x; bl[nt][1] = ub.y;
                }
            }
#pragma unroll
            for (int mt = 0; mt < 2; mt++)
#pragma unroll
                for (int nt = 0; nt < 4; nt++) {
                    MMA_BF16(acc[mt][nt], ah[mt], bh[nt]);
                    if (three) {
                        MMA_BF16(acc[mt][nt], al[mt], bh[nt]);
                        MMA_BF16(acc[mt][nt], ah[mt], bl[nt]);
                    }
                }
        }
        __syncthreads();
    }
#pragma unroll
    for (int mt = 0; mt < 2; mt++)
#pragma unroll
        for (int nt = 0; nt < 4; nt++) {
            int row = m0 + wm*32 + mt*16 + g;
            int col = n0 + wn*32 + nt*8 + (q << 1);
            *(float2*)&g_Call[(size_t)row * WALLP + col] =
                make_float2(acc[mt][nt][0], acc[mt][nt][1]);
            *(float2*)&g_Call[(size_t)(row + 8) * WALLP + col] =
                make_float2(acc[mt][nt][2], acc[mt][nt][3]);
        }
}

// fused: per-row L2 normalize (writes bf16 permuted SF) + gat1 edge scalars
__global__ void norm_edge_kernel(const float* __restrict__ simb,
                                 const float* __restrict__ asrc,
                                 const float* __restrict__ adst) {
    int r = blockIdx.x, tid = threadIdx.x;  // 128 threads
    const float* row = g_Call + (size_t)r * WALLP;
    if (tid < NH) {
        int img = r >> 10;
        float es = 0.f, ed = 0.f;
#pragma unroll
        for (int f = 0; f < NF; f++) {
            float v = row[COL_H1 + tid * NF + f];
            es = fmaf(v, asrc[tid * NF + f], es);
            ed = fmaf(v, adst[tid * NF + f], ed);
        }
        g_ES1[r * NH + tid] = es;
        g_ED1[r * NH + tid] = ed;
        atomicMax(&g_M1[img * NH + tid], fenc(es));
    }
    float ss = 0.f;
    for (int c = tid; c < SD; c += 128) { float v = row[c] + simb[c]; ss += v * v; }
#pragma unroll
    for (int off = 16; off > 0; off >>= 1) ss += __shfl_xor_sync(0xffffffffu, ss, off);
    __shared__ float red[4];
    if ((tid & 31) == 0) red[tid >> 5] = ss;
    __syncthreads();
    float tot = red[0] + red[1] + red[2] + red[3];
    float inv = 1.f / (sqrtf(tot) + 1e-9f);
    for (int c = tid; c < SD; c += 128) {
        float v = (row[c] + simb[c]) * inv;
        int cp = (c & ~15) | kperm(c & 15);
        g_SFb[(size_t)r * SD + cp] = __float2bfloat16_rn(v);
    }
}

// GAT1 aggregation via CSR: block(64) per dst, thread = channel
__global__ void gat1_agg_csr(const float* __restrict__ b1) {
    int gd = blockIdx.x;
    int img = gd >> 10;
    int c = threadIdx.x;         // 0..63
    int h = c >> 3;
    float ed = g_ED1[gd * NH + h];
    float shift = lrelu(fdec(g_M1[img * NH + h]) + ed);
    int cnt = g_e1cnt[gd];
    const int* lst = g_e1 + (size_t)gd * NN;
    float acc = 0.f, den = 0.f;
    for (int e = 0; e < cnt; e++) {
        int s = lst[e];
        int gs = (img << 10) + s;
        float es = g_ES1[gs * NH + h];
        float w = __expf(lrelu(es + ed) - shift);
        den += w;
        acc = fmaf(w, g_Call[(size_t)gs * WALLP + COL_H1 + c], acc);
    }
    float v = acc / den + b1[c];
    g_N1[(size_t)gd * 64 + c] = v > 0.f ? v : expm1f(v);
}

__global__ void gat2_prep_kernel(const float* __restrict__ W2,
                                 const float* __restrict__ asrc2,
                                 const float* __restrict__ adst2) {
    int n = blockIdx.x * blockDim.x + threadIdx.x;
    if (n >= NODES) return;
    int img = n >> 10;
    float x[64];
#pragma unroll
    for (int k = 0; k < 64; k++) x[k] = g_N1[(size_t)n * 64 + k];
    float es = 0.f, ed = 0.f;
    for (int c = 0; c < NC; c++) {
        float a = 0.f;
#pragma unroll
        for (int k = 0; k < 64; k++) a = fmaf(x[k], W2[k * NC + c], a);
        g_H2[n * NC + c] = a;
        es = fmaf(a, asrc2[c], es);
        ed = fmaf(a, adst2[c], ed);
    }
    g_ES2[n] = es;
    g_ED2[n] = ed;
    atomicMax(&g_M2[img], fenc(es));
}

// per-image gram of bf16 sim features -> byte mask (single-pass bf16)
__global__ __launch_bounds__(256, 2) void gram_tc_pipe() {
    extern __shared__ char smem[];
    const int img = blockIdx.z;
    const char* SF = (const char*)(g_SFb + (size_t)img * NN * SD);
    const int t = threadIdx.x;
    const int lane = t & 31, w = t >> 5;
    const int wm = w >> 1, wn = w & 1;
    const int m0 = blockIdx.y * 128;
    const int n0 = blockIdx.x * 64;

    const char* Abase = SF + (size_t)m0 * SD * 2;
    const char* Bbase = SF + (size_t)n0 * SD * 2;

    float acc[2][4][4];
#pragma unroll
    for (int mt = 0; mt < 2; mt++)
#pragma unroll
        for (int nt = 0; nt < 4; nt++)
#pragma unroll
            for (int i = 0; i < 4; i++) acc[mt][nt][i] = 0.f;

    auto stage = [&](int kt, int buf) {
        char* base = smem + buf * GBUFB;
        size_t koff = (size_t)kt * 64;
#pragma unroll
        for (int j = 0; j < 2; j++) {
            int idx = t + j * 256;
            int m = idx >> 2, c = idx & 3;
            int doff = m * 64 + ((c ^ (m & 3)) << 4);
            CP16((unsigned)__cvta_generic_to_shared(base + doff),
                 Abase + (size_t)m * SD * 2 + koff + c * 16);
        }
        {
            int n = t >> 2, c = t & 3;
            int doff = n * 64 + ((c ^ (n & 3)) << 4);
            CP16((unsigned)__cvta_generic_to_shared(base + ATB + doff),
                 Bbase + (size_t)n * SD * 2 + koff + c * 16);
        }
    };

    stage(0, 0);
    CP_COMMIT();
    const int T = SD / 32;
    const int q = lane & 3, g = lane >> 2;
    for (int kt = 0; kt < T; kt++) {
        int cur = kt & 1;
        if (kt + 1 < T) {
            stage(kt + 1, cur ^ 1);
            CP_COMMIT();
            CP_WAIT1();
        } else {
            CP_WAIT0();
        }
        __syncthreads();
        const char* AhS = smem + cur * GBUFB;
        const char* BhS = AhS + ATB;
#pragma unroll
        for (int s = 0; s < 2; s++) {
            unsigned ah[2][4], bh[4][2];
            int sc = (s << 1) | (q >> 1);
            int hb = (q & 1) << 3;
#pragma unroll
            for (int mt = 0; mt < 2; mt++) {
                int r0 = wm*32 + mt*16 + g;
                int off0 = r0 * 64 + ((sc ^ (r0 & 3)) << 4) + hb;
                uint2 v0 = *(const uint2*)(AhS + off0);
                uint2 v1 = *(const uint2*)(AhS + off0 + 512);
                ah[mt][0] = v0.x; ah[mt][1] = v1.x; ah[mt][2] = v0.y; ah[mt][3] = v1.y;
            }
#pragma unroll
            for (int nt = 0; nt < 4; nt++) {
                int n = wn*32 + nt*8 + g;
                int off = n * 64 + ((sc ^ (n & 3)) << 4) + hb;
                uint2 vb = *(const uint2*)(BhS + off);
                bh[nt][0] = vb.x; bh[nt][1] = vb.y;
            }
#pragma unroll
            for (int mt = 0; mt < 2; mt++)
#pragma unroll
                for (int nt = 0; nt < 4; nt++)
                    MMA_BF16(acc[mt][nt], ah[mt], bh[nt]);
        }
        __syncthreads();
    }
    unsigned char* M = g_simM + (size_t)img * NN * NN;
#pragma unroll
    for (int mt = 0; mt < 2; mt++)
#pragma unroll
        for (int nt = 0; nt < 4; nt++) {
            int s0 = m0 + wm*32 + mt*16 + g;
            int d0 = n0 + wn*32 + nt*8 + (q << 1);
            M[(size_t)d0 * NN + s0]       = (unsigned char)((acc[mt][nt][0] >= 0.4f) || (s0 == d0));
            M[(size_t)(d0+1) * NN + s0]   = (unsigned char)((acc[mt][nt][1] >= 0.4f) || (s0 == d0+1));
            M[(size_t)d0 * NN + s0+8]     = (unsigned char)((acc[mt][nt][2] >= 0.4f) || (s0+8 == d0));
            M[(size_t)(d0+1) * NN + s0+8] = (unsigned char)((acc[mt][nt][3] >= 0.4f) || (s0+8 == d0+1));
        }
}

// compact sim byte mask to CSR: warp per dst (ascending s)
__global__ void sim_csr_kernel() {
    int img = blockIdx.y, tid = threadIdx.x;
    int warp = tid >> 5, lane = tid & 31;
    int d = blockIdx.x * 8 + warp;
    int gd = img * NN + d;
    const unsigned char* M = g_simM + (size_t)img * NN * NN + (size_t)d * NN;
    int* lst = g_e2 + (size_t)gd * NN;
    int base = 0;
    for (int p = 0; p < 32; p++) {
        int s = p * 32 + lane;
        bool flag = M[s] != 0;
        unsigned m = __ballot_sync(0xffffffffu, flag);
        if (flag) lst[base + __popc(m & ((1u << lane) - 1u))] = s;
        base += __popc(m);
    }
    if (lane == 0) g_e2cnt[gd] = base;
}

// GAT2 aggregation via CSR: block(32) per dst
__global__ void gat2_agg_csr(const float* __restrict__ b2) {
    int gd = blockIdx.x;
    int img = gd >> 10;
    int c = threadIdx.x;         // 0..31, active c<NC
    float ed = g_ED2[gd];
    float shift = lrelu(fdec(g_M2[img]) + ed);
    int cnt = g_e2cnt[gd];
    const int* lst = g_e2 + (size_t)gd * NN;
    float acc = 0.f, den = 0.f;
    for (int e = 0; e < cnt; e++) {
        int s = lst[e];
        int gs = (img << 10) + s;
        float es = g_ES2[gs];
        float w = __expf(lrelu(es + ed) - shift);
        den += w;
        if (c < NC) acc = fmaf(w, g_H2[gs * NC + c], acc);
    }
    if (c < NC) g_N2[(size_t)gd * NC + c] = acc / den + b2[c];
}

__global__ void node_kernel(const float* __restrict__ nW, const float* __restrict__ nb,
                            float* __restrict__ out) {
    int n = blockIdx.x * blockDim.x + threadIdx.x;
    if (n >= NODES) return;
    float x[NC], v[NC];
#pragma unroll
    for (int c = 0; c < NC; c++) x[c] = g_N2[(size_t)n * NC + c];
#pragma unroll
    for (int c = 0; c < NC; c++) {
        float a = nb[c];
#pragma unroll
        for (int cc = 0; cc < NC; cc++) a = fmaf(x[cc], nW[cc * NC + c], a);
        v[c] = a;
    }
    float m = v[0];
#pragma unroll
    for (int c = 1; c < NC; c++) m = fmaxf(m, v[c]);
    float s = 0.f;
#pragma unroll
    for (int c = 0; c < NC; c++) { v[c] = __expf(v[c] - m); s += v[c]; }
    float inv = 1.f / s;
#pragma unroll
    for (int c = 0; c < NC; c++) out[OUT_NODE + (size_t)n * NC + c] = v[c] * inv;
}

__global__ void graph_kernel(float* __restrict__ out) {
    int img = blockIdx.x, c = blockIdx.y, tid = threadIdx.x;  // 256 threads
    float s = 0.f;
    for (int node = tid; node < NN; node += 256)
        s += out[OUT_NODE + (size_t)(img * NN + node) * NC + c];
#pragma unroll
    for (int off = 16; off > 0; off >>= 1) s += __shfl_xor_sync(0xffffffffu, s, off);
    __shared__ float red[8];
    if ((tid & 31) == 0) red[tid >> 5] = s;
    __syncthreads();
    if (tid == 0) {
        float tot = 0.f;
#pragma unroll
        for (int i = 0; i < 8; i++) tot += red[i];
        out[img * NC + c] = tot * (1.f / (float)NN);
    }
}

__global__ void scatter_kernel(const float* __restrict__ refb, const float* __restrict__ bboxb,
                               float* __restrict__ out) {
    int idx = blockIdx.x * blockDim.x + threadIdx.x;
    const int REF_TOT = 3 * NODES * NC;       // 245760
    const int BBOX_TOT = 3 * NODES * 80;      // 983040
    if (idx < REF_TOT) {
        int k = idx / (NODES * NC), r = idx % (NODES * NC);
        int n = r / NC, c = r % NC;
        out[OUT_REF + idx] = g_Call[(size_t)n * WALLP + COL_REF + k * NC + c] + refb[k * NC + c];
    } else {
        int j = idx - REF_TOT;
        if (j >= BBOX_TOT) return;
        int k = j / (NODES * 80), r = j % (NODES * 80);
        int n = r / 80, c = r % 80;
        out[OUT_BBOX + j] = g_Call[(size_t)n * WALLP + COL_BBOX + k * 80 + c] + bboxb[k * 80 + c];
    }
}

// ---------------- launch ----------------
extern "C" void kernel_launch(void* const* d_in, const int* in_sizes, int n_in,
                              void* d_out, int out_size) {
    const float* x1     = (const float*)d_in[0];
    const float* boxes  = (const float*)d_in[1];
    const float* simW   = (const float*)d_in[2];
    const float* simb   = (const float*)d_in[3];
    const float* gat1W  = (const float*)d_in[4];
    const float* asrc1  = (const float*)d_in[5];
    const float* adst1  = (const float*)d_in[6];
    const float* b1     = (const float*)d_in[7];
    const float* gat2W  = (const float*)d_in[8];
    const float* asrc2  = (const float*)d_in[9];
    const float* adst2  = (const float*)d_in[10];
    const float* b2     = (const float*)d_in[11];
    const float* nodeW  = (const float*)d_in[12];
    const float* nodeb  = (const float*)d_in[13];
    const float* refW   = (const float*)d_in[14];
    const float* refb   = (const float*)d_in[15];
    const float* bboxW  = (const float*)d_in[16];
    const float* bboxb  = (const float*)d_in[17];
    float* out = (float*)d_out;

    cudaFuncSetAttribute(sgemm_tc_pipe, cudaFuncAttributeMaxDynamicSharedMemorySize, SGEMM_SMEM);
    cudaFuncSetAttribute(gram_tc_pipe,  cudaFuncAttributeMaxDynamicSharedMemorySize, GRAM_SMEM);

    splitA_kernel<<<NODES * DIN / 16 / 256, 256>>>(x1);
    pack_kernel<<<dim3(WALLP / 32, DIN / 32), dim3(32, 8)>>>(simW, gat1W, refW, bboxW);
    iou_csr_kernel<<<dim3(NN / 8, BI), 256>>>(boxes);
    sgemm_tc_pipe<<<NBX * NBY, 256, SGEMM_SMEM>>>();
    norm_edge_kernel<<<NODES, 128>>>(simb, asrc1, adst1);
    gat1_agg_csr<<<NODES, 64>>>(b1);
    gat2_prep_kernel<<<NODES / 256, 256>>>(gat2W, asrc2, adst2);
    gram_tc_pipe<<<dim3(NN / 64, NN / 128, BI), 256, GRAM_SMEM>>>();
    sim_csr_kernel<<<dim3(NN / 8, BI), 256>>>();
    gat2_agg_csr<<<NODES, 32>>>(b2);
    node_kernel<<<NODES / 256, 256>>>(nodeW, nodeb, out);
    graph_kernel<<<dim3(BI, NC), 256>>>(out);
    scatter_kernel<<<(3 * NODES * NC + 3 * NODES * 80 + 255) / 256, 256>>>(refb, bboxb, out);
}